// round 1
// baseline (speedup 1.0000x reference)
#include <cuda_runtime.h>
#include <cstdint>

#define D_MODEL   1024
#define NUM_HEADS 16
#define D_HEAD    64
#define BATCH     4
#define SEQ       2048
#define MTOT      (BATCH * SEQ)   // 8192

// ---------------- scratch (device globals: allocation-guard safe) ----------
__device__ float g_q[BATCH * NUM_HEADS * SEQ * D_HEAD];   // 32 MB, [b,h,s,d]
__device__ float g_k[BATCH * NUM_HEADS * SEQ * D_HEAD];   // 32 MB
__device__ float g_v[BATCH * NUM_HEADS * SEQ * D_HEAD];   // 32 MB
__device__ float g_ctx[MTOT * D_MODEL];                   // 32 MB, [b,s,h*d]

// ---------------- GEMM: C[m,n] = sum_k A[m,k] * W[n,k]  (y = x @ W^T) ------
#define BM 128
#define BN 128
#define BK 16

// Shared GEMM body. A: [M=8192, K=1024] row-major. W: [N', K=1024] row-major.
// Produces acc[8][8] for this thread's 8x8 micro-tile of the 128x128 block.
__device__ __forceinline__ void gemm_body(const float* __restrict__ A,
                                          const float* __restrict__ W,
                                          int m0, int n0,
                                          float (&acc)[8][8],
                                          float (*As)[BM + 4],
                                          float (*Bs)[BN + 4],
                                          int tid)
{
    const int row  = tid >> 1;          // 0..127
    const int kseg = (tid & 1) * 8;     // 0 or 8
    const int tx   = tid & 15;
    const int ty   = tid >> 4;

    for (int k0 = 0; k0 < D_MODEL; k0 += BK) {
        // ---- load tiles (transposed into smem: [k][m] / [k][n]) ----
        float4 a0 = *(const float4*)&A[(size_t)(m0 + row) * D_MODEL + k0 + kseg];
        float4 a1 = *(const float4*)&A[(size_t)(m0 + row) * D_MODEL + k0 + kseg + 4];
        float4 b0 = *(const float4*)&W[(size_t)(n0 + row) * D_MODEL + k0 + kseg];
        float4 b1 = *(const float4*)&W[(size_t)(n0 + row) * D_MODEL + k0 + kseg + 4];

        As[kseg + 0][row] = a0.x; As[kseg + 1][row] = a0.y;
        As[kseg + 2][row] = a0.z; As[kseg + 3][row] = a0.w;
        As[kseg + 4][row] = a1.x; As[kseg + 5][row] = a1.y;
        As[kseg + 6][row] = a1.z; As[kseg + 7][row] = a1.w;

        Bs[kseg + 0][row] = b0.x; Bs[kseg + 1][row] = b0.y;
        Bs[kseg + 2][row] = b0.z; Bs[kseg + 3][row] = b0.w;
        Bs[kseg + 4][row] = b1.x; Bs[kseg + 5][row] = b1.y;
        Bs[kseg + 6][row] = b1.z; Bs[kseg + 7][row] = b1.w;

        __syncthreads();

        // ---- compute ----
        #pragma unroll
        for (int k = 0; k < BK; k++) {
            float4 av0 = *(const float4*)&As[k][ty * 8];
            float4 av1 = *(const float4*)&As[k][ty * 8 + 4];
            float4 bv0 = *(const float4*)&Bs[k][tx * 8];
            float4 bv1 = *(const float4*)&Bs[k][tx * 8 + 4];
            float a[8] = {av0.x, av0.y, av0.z, av0.w, av1.x, av1.y, av1.z, av1.w};
            float b[8] = {bv0.x, bv0.y, bv0.z, bv0.w, bv1.x, bv1.y, bv1.z, bv1.w};
            #pragma unroll
            for (int i = 0; i < 8; i++)
                #pragma unroll
                for (int j = 0; j < 8; j++)
                    acc[i][j] = fmaf(a[i], b[j], acc[i][j]);
        }
        __syncthreads();
    }
}

// Fused QKV projection. blockIdx.z selects weight/destination.
// Output layout: [b, h, s, d].
__global__ __launch_bounds__(256) void gemm_qkv(const float* __restrict__ x,
                                                const float* __restrict__ Qw,
                                                const float* __restrict__ Kw,
                                                const float* __restrict__ Vw)
{
    __shared__ float As[BK][BM + 4];
    __shared__ float Bs[BK][BN + 4];
    float acc[8][8] = {};

    const int m0 = blockIdx.y * BM;
    const int n0 = blockIdx.x * BN;
    const int z  = blockIdx.z;
    const float* W = (z == 0) ? Qw : (z == 1) ? Kw : Vw;

    gemm_body(x, W, m0, n0, acc, As, Bs, threadIdx.x);

    float* dst = (z == 0) ? g_q : (z == 1) ? g_k : g_v;
    const int tx = threadIdx.x & 15, ty = threadIdx.x >> 4;
    #pragma unroll
    for (int i = 0; i < 8; i++) {
        const int m = m0 + ty * 8 + i;
        const int b = m >> 11;          // /2048
        const int s = m & 2047;
        #pragma unroll
        for (int j = 0; j < 8; j++) {
            const int n = n0 + tx * 8 + j;
            const int h = n >> 6;
            const int d = n & 63;
            dst[((size_t)(b * NUM_HEADS + h) * SEQ + s) * D_HEAD + d] = acc[i][j];
        }
    }
}

// Output projection: out = ctx @ Ow^T, plain [M, N] output.
__global__ __launch_bounds__(256) void gemm_out(const float* __restrict__ Ow,
                                                float* __restrict__ out)
{
    __shared__ float As[BK][BM + 4];
    __shared__ float Bs[BK][BN + 4];
    float acc[8][8] = {};

    const int m0 = blockIdx.y * BM;
    const int n0 = blockIdx.x * BN;

    gemm_body(g_ctx, Ow, m0, n0, acc, As, Bs, threadIdx.x);

    const int tx = threadIdx.x & 15, ty = threadIdx.x >> 4;
    #pragma unroll
    for (int i = 0; i < 8; i++) {
        const int m = m0 + ty * 8 + i;
        #pragma unroll
        for (int j = 0; j < 8; j++) {
            const int n = n0 + tx * 8 + j;
            out[(size_t)m * D_MODEL + n] = acc[i][j];
        }
    }
}

// ---------------- Flash attention (fp32, causal) ---------------------------
// Block = one (b, h, 64-query tile). 256 threads as 16x16; each thread owns a
// 4x4 micro-tile of the 64x64 score tile and a 4x4 micro-tile of O.
#define BQ   64
#define BKV  64
#define KSTR 68   // padded stride (floats) for K/P and V^T tiles

// dynamic smem: Qs[64*64] + Ks[64*KSTR] (reused for P) + Vst[64*KSTR]
#define ATTN_SMEM_BYTES ((64 * 64 + 64 * KSTR + 64 * KSTR) * 4)

__global__ __launch_bounds__(256) void attn_kernel(const unsigned char* __restrict__ pm)
{
    extern __shared__ float sm[];
    float* Qs  = sm;                   // [r][d], stride 64
    float* Ks  = sm + 64 * 64;         // [c][d], stride KSTR; reused as P[r][c]
    float* Vst = Ks + 64 * KSTR;       // [d][c], stride KSTR

    const int qt  = blockIdx.x;
    const int h   = blockIdx.y;
    const int b   = blockIdx.z;
    const int tid = threadIdx.x;
    const int tx  = tid & 15;
    const int ty  = tid >> 4;

    const size_t base = (size_t)(b * NUM_HEADS + h) * SEQ;   // row base into [BH, S]

    // ---- load Q tile (coalesced float4) ----
    {
        const int r  = tid >> 2;            // 0..63
        const int cs = (tid & 3) * 16;      // 0/16/32/48
        const float* src = g_q + (base + (size_t)qt * BQ + r) * D_HEAD + cs;
        float* dst = Qs + r * 64 + cs;
        #pragma unroll
        for (int u = 0; u < 4; u++)
            ((float4*)dst)[u] = ((const float4*)src)[u];
    }

    float m_i[4], l_i[4], o[4][4];
    #pragma unroll
    for (int i = 0; i < 4; i++) {
        m_i[i] = -1e30f; l_i[i] = 0.f;
        #pragma unroll
        for (int j = 0; j < 4; j++) o[i][j] = 0.f;
    }

    for (int kt = 0; kt <= qt; kt++) {
        __syncthreads();  // prev-iter P/V readers done (also orders Q writes)

        // ---- load K tile [c][d] and V tile transposed [d][c] ----
        {
            const int r  = tid >> 2;
            const int cs = (tid & 3) * 16;
            const size_t grow = base + (size_t)kt * BKV + r;
            const float* ksrc = g_k + grow * D_HEAD + cs;
            float* kdst = Ks + r * KSTR + cs;
            #pragma unroll
            for (int u = 0; u < 4; u++)
                ((float4*)kdst)[u] = ((const float4*)ksrc)[u];

            const float* vsrc = g_v + grow * D_HEAD + cs;
            #pragma unroll
            for (int u = 0; u < 4; u++) {
                float4 vv = ((const float4*)vsrc)[u];
                const int d = cs + u * 4;
                Vst[(d + 0) * KSTR + r] = vv.x;
                Vst[(d + 1) * KSTR + r] = vv.y;
                Vst[(d + 2) * KSTR + r] = vv.z;
                Vst[(d + 3) * KSTR + r] = vv.w;
            }
        }
        __syncthreads();

        // ---- scores: S[r][c] = (q . k) * 0.125 ----
        float s[4][4] = {};
        #pragma unroll
        for (int d = 0; d < 64; d += 4) {
            float4 qv[4], kv[4];
            #pragma unroll
            for (int i = 0; i < 4; i++)
                qv[i] = *(const float4*)&Qs[(ty * 4 + i) * 64 + d];
            #pragma unroll
            for (int j = 0; j < 4; j++)
                kv[j] = *(const float4*)&Ks[(tx * 4 + j) * KSTR + d];
            #pragma unroll
            for (int i = 0; i < 4; i++)
                #pragma unroll
                for (int j = 0; j < 4; j++) {
                    s[i][j] = fmaf(qv[i].x, kv[j].x, s[i][j]);
                    s[i][j] = fmaf(qv[i].y, kv[j].y, s[i][j]);
                    s[i][j] = fmaf(qv[i].z, kv[j].z, s[i][j]);
                    s[i][j] = fmaf(qv[i].w, kv[j].w, s[i][j]);
                }
        }

        // ---- scale + causal + padding masks ----
        unsigned char pmj[4];
        {
            const unsigned char* pmb = pm + (size_t)b * SEQ + (size_t)kt * BKV + tx * 4;
            #pragma unroll
            for (int j = 0; j < 4; j++) pmj[j] = pmb[j];
        }
        const bool diag = (kt == qt);
        #pragma unroll
        for (int i = 0; i < 4; i++)
            #pragma unroll
            for (int j = 0; j < 4; j++) {
                float v = s[i][j] * 0.125f;
                if (diag && (tx * 4 + j) > (ty * 4 + i)) v = -1e30f;
                if (pmj[j]) v = -1e30f;
                s[i][j] = v;
            }

        // ---- online softmax update (row reduce over 16 tx lanes) ----
        #pragma unroll
        for (int i = 0; i < 4; i++) {
            float rm = fmaxf(fmaxf(s[i][0], s[i][1]), fmaxf(s[i][2], s[i][3]));
            #pragma unroll
            for (int off = 8; off >= 1; off >>= 1)
                rm = fmaxf(rm, __shfl_xor_sync(0xffffffffu, rm, off));
            const float mn    = fmaxf(m_i[i], rm);
            const float alpha = __expf(m_i[i] - mn);
            m_i[i] = mn;
            float rs = 0.f;
            #pragma unroll
            for (int j = 0; j < 4; j++) {
                s[i][j] = __expf(s[i][j] - mn);
                rs += s[i][j];
            }
            #pragma unroll
            for (int off = 8; off >= 1; off >>= 1)
                rs += __shfl_xor_sync(0xffffffffu, rs, off);
            l_i[i] = l_i[i] * alpha + rs;
            #pragma unroll
            for (int j = 0; j < 4; j++) o[i][j] *= alpha;
        }

        __syncthreads();   // everyone done reading Ks

        // ---- store P into Ks buffer ----
        #pragma unroll
        for (int i = 0; i < 4; i++)
            *(float4*)&Ks[(ty * 4 + i) * KSTR + tx * 4] =
                make_float4(s[i][0], s[i][1], s[i][2], s[i][3]);
        __syncthreads();

        // ---- O += P @ V  (O[r][dv], dv = tx*4+j, via V^T) ----
        #pragma unroll
        for (int c = 0; c < 64; c += 4) {
            float4 pv[4], vv[4];
            #pragma unroll
            for (int i = 0; i < 4; i++)
                pv[i] = *(const float4*)&Ks[(ty * 4 + i) * KSTR + c];
            #pragma unroll
            for (int j = 0; j < 4; j++)
                vv[j] = *(const float4*)&Vst[(tx * 4 + j) * KSTR + c];
            #pragma unroll
            for (int i = 0; i < 4; i++)
                #pragma unroll
                for (int j = 0; j < 4; j++) {
                    o[i][j] = fmaf(pv[i].x, vv[j].x, o[i][j]);
                    o[i][j] = fmaf(pv[i].y, vv[j].y, o[i][j]);
                    o[i][j] = fmaf(pv[i].z, vv[j].z, o[i][j]);
                    o[i][j] = fmaf(pv[i].w, vv[j].w, o[i][j]);
                }
        }
    }

    // ---- normalize and write ctx [b, s, h*64 + dv] ----
    #pragma unroll
    for (int i = 0; i < 4; i++) {
        const float inv = 1.f / l_i[i];
        const int srow = qt * BQ + ty * 4 + i;
        float* dst = g_ctx + ((size_t)b * SEQ + srow) * D_MODEL + h * D_HEAD + tx * 4;
        *(float4*)dst = make_float4(o[i][0] * inv, o[i][1] * inv,
                                    o[i][2] * inv, o[i][3] * inv);
    }
}

// ---------------- launch ----------------------------------------------------
extern "C" void kernel_launch(void* const* d_in, const int* in_sizes, int n_in,
                              void* d_out, int out_size)
{
    (void)in_sizes; (void)n_in; (void)out_size;
    const float* x  = (const float*)d_in[0];
    const float* Qw = (const float*)d_in[1];
    const float* Kw = (const float*)d_in[2];
    const float* Vw = (const float*)d_in[3];
    const float* Ow = (const float*)d_in[4];
    const unsigned char* pm = (const unsigned char*)d_in[5];
    float* out = (float*)d_out;

    // 51.2 KB dynamic smem > 48 KB default: opt in (host-side attr, capture-safe)
    cudaFuncSetAttribute(attn_kernel,
                         cudaFuncAttributeMaxDynamicSharedMemorySize,
                         ATTN_SMEM_BYTES);

    dim3 gq(D_MODEL / BN, MTOT / BM, 3);          // 8 x 64 x 3
    gemm_qkv<<<gq, 256>>>(x, Qw, Kw, Vw);

    dim3 ga(SEQ / BQ, NUM_HEADS, BATCH);          // 32 x 16 x 4
    attn_kernel<<<ga, 256, ATTN_SMEM_BYTES>>>(pm);

    dim3 go(D_MODEL / BN, MTOT / BM);             // 8 x 64
    gemm_out<<<go, 256>>>(Ow, out);
}

// round 2
// speedup vs baseline: 2.0094x; 2.0094x over previous
#include <cuda_runtime.h>
#include <cstdint>

#define D_MODEL   1024
#define NUM_HEADS 16
#define D_HEAD    64
#define BATCH     4
#define SEQ       2048
#define MTOT      (BATCH * SEQ)   // 8192

// ---------------- scratch (device globals: allocation-guard safe) ----------
__device__ float g_q[BATCH * NUM_HEADS * SEQ * D_HEAD];   // [b,h,s,d]
__device__ float g_k[BATCH * NUM_HEADS * SEQ * D_HEAD];
__device__ float g_v[BATCH * NUM_HEADS * SEQ * D_HEAD];
__device__ float g_ctx[MTOT * D_MODEL];                   // [b,s,h*d]

// ---------------- tf32 helpers ---------------------------------------------
__device__ __forceinline__ unsigned f32_to_tf32(float x) {
    unsigned u;
    asm("cvt.rna.tf32.f32 %0, %1;" : "=r"(u) : "f"(x));
    return u;
}
__device__ __forceinline__ void split_tf32(float x, unsigned& hi, unsigned& lo) {
    hi = f32_to_tf32(x);
    lo = f32_to_tf32(x - __uint_as_float(hi));
}
// D += A(16x8) * B(8x8); A row-major frags, B col-major frags, fp32 accum.
__device__ __forceinline__ void mma8(float* c, const unsigned* a, unsigned b0, unsigned b1) {
    asm volatile(
        "mma.sync.aligned.m16n8k8.row.col.f32.tf32.tf32.f32 "
        "{%0,%1,%2,%3}, {%4,%5,%6,%7}, {%8,%9}, {%0,%1,%2,%3};"
        : "+f"(c[0]), "+f"(c[1]), "+f"(c[2]), "+f"(c[3])
        : "r"(a[0]), "r"(a[1]), "r"(a[2]), "r"(a[3]), "r"(b0), "r"(b1));
}

// ---------------- 3xTF32 GEMM: C[m,n] = sum_k A[m,k] * W[n,k] ---------------
// Block tile 128x128, BK=32, 256 threads = 8 warps (4m x 2n), warp tile 32x64.
#define GSTR 36

__device__ __forceinline__ void gemm3_body(const float* __restrict__ A,
                                           const float* __restrict__ W,
                                           int m0, int n0,
                                           float (&c)[2][8][4],
                                           float* As, float* Bs)
{
    const int tid  = threadIdx.x;
    const int lane = tid & 31;
    const int g    = lane >> 2;
    const int t    = lane & 3;
    const int warp = tid >> 5;
    const int wm   = (warp >> 1) * 32;
    const int wn   = (warp & 1) * 64;

    int rowL[4], colL[4];
    #pragma unroll
    for (int u = 0; u < 4; u++) {
        int lin = tid + 256 * u;
        rowL[u] = lin >> 3;
        colL[u] = (lin & 7) * 4;
    }

    float4 pa[4], pb[4];
    #pragma unroll
    for (int u = 0; u < 4; u++) {
        pa[u] = *(const float4*)&A[(size_t)(m0 + rowL[u]) * D_MODEL + colL[u]];
        pb[u] = *(const float4*)&W[(size_t)(n0 + rowL[u]) * D_MODEL + colL[u]];
    }

    for (int k0 = 0; k0 < D_MODEL; k0 += 32) {
        #pragma unroll
        for (int u = 0; u < 4; u++) {
            *(float4*)&As[rowL[u] * GSTR + colL[u]] = pa[u];
            *(float4*)&Bs[rowL[u] * GSTR + colL[u]] = pb[u];
        }
        __syncthreads();

        if (k0 + 32 < D_MODEL) {
            #pragma unroll
            for (int u = 0; u < 4; u++) {
                pa[u] = *(const float4*)&A[(size_t)(m0 + rowL[u]) * D_MODEL + k0 + 32 + colL[u]];
                pb[u] = *(const float4*)&W[(size_t)(n0 + rowL[u]) * D_MODEL + k0 + 32 + colL[u]];
            }
        }

        #pragma unroll
        for (int ks = 0; ks < 4; ks++) {
            const int k = ks * 8;
            unsigned ahi[2][4], alo[2][4];
            #pragma unroll
            for (int i = 0; i < 2; i++) {
                const int r = wm + 16 * i;
                split_tf32(As[(r + g    ) * GSTR + k + t    ], ahi[i][0], alo[i][0]);
                split_tf32(As[(r + g + 8) * GSTR + k + t    ], ahi[i][1], alo[i][1]);
                split_tf32(As[(r + g    ) * GSTR + k + t + 4], ahi[i][2], alo[i][2]);
                split_tf32(As[(r + g + 8) * GSTR + k + t + 4], ahi[i][3], alo[i][3]);
            }
            #pragma unroll
            for (int j = 0; j < 8; j++) {
                const int br = wn + 8 * j + g;
                unsigned bh0, bl0, bh1, bl1;
                split_tf32(Bs[br * GSTR + k + t    ], bh0, bl0);
                split_tf32(Bs[br * GSTR + k + t + 4], bh1, bl1);
                #pragma unroll
                for (int i = 0; i < 2; i++) {
                    mma8(c[i][j], ahi[i], bh0, bh1);
                    mma8(c[i][j], alo[i], bh0, bh1);
                    mma8(c[i][j], ahi[i], bl0, bl1);
                }
            }
        }
        __syncthreads();
    }
}

// Fused QKV projection; blockIdx.z selects weight. Output [b,h,s,d].
__global__ __launch_bounds__(256) void gemm_qkv(const float* __restrict__ x,
                                                const float* __restrict__ Qw,
                                                const float* __restrict__ Kw,
                                                const float* __restrict__ Vw)
{
    __shared__ float As[128 * GSTR];
    __shared__ float Bs[128 * GSTR];
    float c[2][8][4];
    #pragma unroll
    for (int i = 0; i < 2; i++)
        #pragma unroll
        for (int j = 0; j < 8; j++)
            #pragma unroll
            for (int q = 0; q < 4; q++) c[i][j][q] = 0.f;

    const int m0 = blockIdx.y * 128;
    const int n0 = blockIdx.x * 128;
    const int z  = blockIdx.z;
    const float* W = (z == 0) ? Qw : (z == 1) ? Kw : Vw;

    gemm3_body(x, W, m0, n0, c, As, Bs);

    float* dst = (z == 0) ? g_q : (z == 1) ? g_k : g_v;
    const int lane = threadIdx.x & 31;
    const int g = lane >> 2, t = lane & 3;
    const int warp = threadIdx.x >> 5;
    const int wm = (warp >> 1) * 32, wn = (warp & 1) * 64;

    #pragma unroll
    for (int i = 0; i < 2; i++) {
        #pragma unroll
        for (int j = 0; j < 8; j++) {
            const int n = n0 + wn + 8 * j + 2 * t;
            const int h = n >> 6, d = n & 63;
            const int r0 = m0 + wm + 16 * i + g;
            const int r1 = r0 + 8;
            const int b0 = r0 >> 11, s0 = r0 & 2047;
            const int b1 = r1 >> 11, s1 = r1 & 2047;
            *(float2*)&dst[((size_t)(b0 * NUM_HEADS + h) * SEQ + s0) * D_HEAD + d] =
                make_float2(c[i][j][0], c[i][j][1]);
            *(float2*)&dst[((size_t)(b1 * NUM_HEADS + h) * SEQ + s1) * D_HEAD + d] =
                make_float2(c[i][j][2], c[i][j][3]);
        }
    }
}

// Output projection: out = ctx @ Ow^T, row-major [MTOT, D_MODEL].
__global__ __launch_bounds__(256) void gemm_out(const float* __restrict__ Ow,
                                                float* __restrict__ out)
{
    __shared__ float As[128 * GSTR];
    __shared__ float Bs[128 * GSTR];
    float c[2][8][4];
    #pragma unroll
    for (int i = 0; i < 2; i++)
        #pragma unroll
        for (int j = 0; j < 8; j++)
            #pragma unroll
            for (int q = 0; q < 4; q++) c[i][j][q] = 0.f;

    const int m0 = blockIdx.y * 128;
    const int n0 = blockIdx.x * 128;

    gemm3_body(g_ctx, Ow, m0, n0, c, As, Bs);

    const int lane = threadIdx.x & 31;
    const int g = lane >> 2, t = lane & 3;
    const int warp = threadIdx.x >> 5;
    const int wm = (warp >> 1) * 32, wn = (warp & 1) * 64;

    #pragma unroll
    for (int i = 0; i < 2; i++) {
        #pragma unroll
        for (int j = 0; j < 8; j++) {
            const int n  = n0 + wn + 8 * j + 2 * t;
            const int r0 = m0 + wm + 16 * i + g;
            *(float2*)&out[(size_t)r0 * D_MODEL + n] = make_float2(c[i][j][0], c[i][j][1]);
            *(float2*)&out[(size_t)(r0 + 8) * D_MODEL + n] = make_float2(c[i][j][2], c[i][j][3]);
        }
    }
}

// ---------------- Flash attention with 3xTF32 mma ---------------------------
// Block = (b, h, 64-q-tile). 128 threads = 4 warps; warp w owns q rows
// [16w, 16w+16). Scores/O live in m16n8k8 C-fragments.
#define QSTR 68
#define VSTR 72
#define ATTN_SMEM ((64 * QSTR * 2 + 64 * VSTR) * 4)   // Qs + Ks(/Ps) + Vs

__global__ __launch_bounds__(128) void attn_mma(const unsigned char* __restrict__ pm)
{
    extern __shared__ float smf[];
    float* Qs = smf;                 // [64][QSTR]
    float* Ks = smf + 64 * QSTR;     // [64][QSTR], reused as P
    float* Vs = Ks  + 64 * QSTR;     // [64][VSTR]

    const int qt = blockIdx.x, h = blockIdx.y, b = blockIdx.z;
    const int tid  = threadIdx.x;
    const int lane = tid & 31;
    const int warp = tid >> 5;
    const int g = lane >> 2, t = lane & 3;
    const size_t base = (size_t)(b * NUM_HEADS + h) * SEQ;

    // load Q tile [64][64]
    #pragma unroll
    for (int u = 0; u < 8; u++) {
        int lin = tid + 128 * u;
        int row = lin >> 4, c4 = (lin & 15) * 4;
        *(float4*)&Qs[row * QSTR + c4] =
            *(const float4*)&g_q[(base + (size_t)qt * 64 + row) * D_HEAD + c4];
    }

    float o[8][4];
    float m_i[2] = {-1e30f, -1e30f};
    float l_i[2] = {0.f, 0.f};
    #pragma unroll
    for (int j = 0; j < 8; j++)
        #pragma unroll
        for (int q = 0; q < 4; q++) o[j][q] = 0.f;

    for (int kt = 0; kt <= qt; kt++) {
        __syncthreads();   // prior-iter readers of Ks/Vs done; Qs visible (iter 0)

        #pragma unroll
        for (int u = 0; u < 8; u++) {
            int lin = tid + 128 * u;
            int row = lin >> 4, c4 = (lin & 15) * 4;
            const size_t grow = base + (size_t)kt * 64 + row;
            *(float4*)&Ks[row * QSTR + c4] = *(const float4*)&g_k[grow * D_HEAD + c4];
            *(float4*)&Vs[row * VSTR + c4] = *(const float4*)&g_v[grow * D_HEAD + c4];
        }
        __syncthreads();

        // ---- S = Q @ K^T (3xTF32) ----
        float s[8][4];
        #pragma unroll
        for (int j = 0; j < 8; j++)
            #pragma unroll
            for (int q = 0; q < 4; q++) s[j][q] = 0.f;

        const int r = warp * 16;
        #pragma unroll
        for (int ks = 0; ks < 8; ks++) {
            const int k = ks * 8;
            unsigned ahi[4], alo[4];
            split_tf32(Qs[(r + g    ) * QSTR + k + t    ], ahi[0], alo[0]);
            split_tf32(Qs[(r + g + 8) * QSTR + k + t    ], ahi[1], alo[1]);
            split_tf32(Qs[(r + g    ) * QSTR + k + t + 4], ahi[2], alo[2]);
            split_tf32(Qs[(r + g + 8) * QSTR + k + t + 4], ahi[3], alo[3]);
            #pragma unroll
            for (int j = 0; j < 8; j++) {
                unsigned bh0, bl0, bh1, bl1;
                split_tf32(Ks[(8 * j + g) * QSTR + k + t    ], bh0, bl0);
                split_tf32(Ks[(8 * j + g) * QSTR + k + t + 4], bh1, bl1);
                mma8(s[j], ahi, bh0, bh1);
                mma8(s[j], alo, bh0, bh1);
                mma8(s[j], ahi, bl0, bl1);
            }
        }

        // ---- scale + causal + padding masks ----
        const unsigned char* pmb = pm + (size_t)b * SEQ + (size_t)kt * 64;
        const int r0 = r + g, r1 = r0 + 8;         // local q rows
        const bool diag = (kt == qt);
        #pragma unroll
        for (int j = 0; j < 8; j++) {
            const int c0 = 8 * j + 2 * t, c1 = c0 + 1;
            const bool p0 = pmb[c0] != 0, p1 = pmb[c1] != 0;
            float v;
            v = s[j][0] * 0.125f; if ((diag && c0 > r0) || p0) v = -1e30f; s[j][0] = v;
            v = s[j][1] * 0.125f; if ((diag && c1 > r0) || p1) v = -1e30f; s[j][1] = v;
            v = s[j][2] * 0.125f; if ((diag && c0 > r1) || p0) v = -1e30f; s[j][2] = v;
            v = s[j][3] * 0.125f; if ((diag && c1 > r1) || p1) v = -1e30f; s[j][3] = v;
        }

        // ---- online softmax (rows r0, r1; reduce over quad lanes) ----
        #pragma unroll
        for (int rr = 0; rr < 2; rr++) {
            float rm = -1e30f;
            #pragma unroll
            for (int j = 0; j < 8; j++)
                rm = fmaxf(rm, fmaxf(s[j][2 * rr], s[j][2 * rr + 1]));
            rm = fmaxf(rm, __shfl_xor_sync(0xffffffffu, rm, 1));
            rm = fmaxf(rm, __shfl_xor_sync(0xffffffffu, rm, 2));
            const float mn    = fmaxf(m_i[rr], rm);
            const float alpha = __expf(m_i[rr] - mn);
            m_i[rr] = mn;
            float rs = 0.f;
            #pragma unroll
            for (int j = 0; j < 8; j++) {
                s[j][2 * rr    ] = __expf(s[j][2 * rr    ] - mn);
                s[j][2 * rr + 1] = __expf(s[j][2 * rr + 1] - mn);
                rs += s[j][2 * rr] + s[j][2 * rr + 1];
            }
            rs += __shfl_xor_sync(0xffffffffu, rs, 1);
            rs += __shfl_xor_sync(0xffffffffu, rs, 2);
            l_i[rr] = l_i[rr] * alpha + rs;
            #pragma unroll
            for (int j = 0; j < 8; j++) {
                o[j][2 * rr    ] *= alpha;
                o[j][2 * rr + 1] *= alpha;
            }
        }

        __syncthreads();   // all warps done reading Ks

        // ---- write P (C-frag layout -> row-major smem) ----
        #pragma unroll
        for (int j = 0; j < 8; j++) {
            *(float2*)&Ks[(r0    ) * QSTR + 8 * j + 2 * t] = make_float2(s[j][0], s[j][1]);
            *(float2*)&Ks[(r0 + 8) * QSTR + 8 * j + 2 * t] = make_float2(s[j][2], s[j][3]);
        }
        __syncthreads();

        // ---- O += P @ V (3xTF32); V row-major is the .col B operand ----
        #pragma unroll
        for (int cc = 0; cc < 8; cc++) {
            const int kk = cc * 8;
            unsigned ahi[4], alo[4];
            split_tf32(Ks[(r + g    ) * QSTR + kk + t    ], ahi[0], alo[0]);
            split_tf32(Ks[(r + g + 8) * QSTR + kk + t    ], ahi[1], alo[1]);
            split_tf32(Ks[(r + g    ) * QSTR + kk + t + 4], ahi[2], alo[2]);
            split_tf32(Ks[(r + g + 8) * QSTR + kk + t + 4], ahi[3], alo[3]);
            #pragma unroll
            for (int j = 0; j < 8; j++) {
                unsigned bh0, bl0, bh1, bl1;
                split_tf32(Vs[(kk + t    ) * VSTR + 8 * j + g], bh0, bl0);
                split_tf32(Vs[(kk + t + 4) * VSTR + 8 * j + g], bh1, bl1);
                mma8(o[j], ahi, bh0, bh1);
                mma8(o[j], alo, bh0, bh1);
                mma8(o[j], ahi, bl0, bl1);
            }
        }
    }

    // ---- normalize + write ctx [b, s, h*64 + col] ----
    const float inv0 = 1.f / l_i[0];
    const float inv1 = 1.f / l_i[1];
    const int row0 = qt * 64 + warp * 16 + g;
    float* d0 = g_ctx + ((size_t)b * SEQ + row0    ) * D_MODEL + h * D_HEAD;
    float* d1 = g_ctx + ((size_t)b * SEQ + row0 + 8) * D_MODEL + h * D_HEAD;
    #pragma unroll
    for (int j = 0; j < 8; j++) {
        const int cidx = 8 * j + 2 * t;
        *(float2*)&d0[cidx] = make_float2(o[j][0] * inv0, o[j][1] * inv0);
        *(float2*)&d1[cidx] = make_float2(o[j][2] * inv1, o[j][3] * inv1);
    }
}

// ---------------- launch ----------------------------------------------------
extern "C" void kernel_launch(void* const* d_in, const int* in_sizes, int n_in,
                              void* d_out, int out_size)
{
    (void)in_sizes; (void)n_in; (void)out_size;
    const float* x  = (const float*)d_in[0];
    const float* Qw = (const float*)d_in[1];
    const float* Kw = (const float*)d_in[2];
    const float* Vw = (const float*)d_in[3];
    const float* Ow = (const float*)d_in[4];
    const unsigned char* pm = (const unsigned char*)d_in[5];
    float* out = (float*)d_out;

    cudaFuncSetAttribute(attn_mma,
                         cudaFuncAttributeMaxDynamicSharedMemorySize,
                         ATTN_SMEM);

    dim3 gq(D_MODEL / 128, MTOT / 128, 3);        // 8 x 64 x 3
    gemm_qkv<<<gq, 256>>>(x, Qw, Kw, Vw);

    dim3 ga(SEQ / 64, NUM_HEADS, BATCH);          // 32 x 16 x 4
    attn_mma<<<ga, 128, ATTN_SMEM>>>(pm);

    dim3 go(D_MODEL / 128, MTOT / 128);           // 8 x 64
    gemm_out<<<go, 256>>>(Ow, out);
}

// round 3
// speedup vs baseline: 2.1327x; 1.0614x over previous
#include <cuda_runtime.h>
#include <cstdint>

#define D_MODEL   1024
#define NUM_HEADS 16
#define D_HEAD    64
#define BATCH     4
#define SEQ       2048
#define MTOT      (BATCH * SEQ)   // 8192

// ---------------- scratch (device globals: allocation-guard safe) ----------
__device__ float g_q[BATCH * NUM_HEADS * SEQ * D_HEAD];   // [b,h,s,d]
__device__ float g_k[BATCH * NUM_HEADS * SEQ * D_HEAD];
__device__ float g_v[BATCH * NUM_HEADS * SEQ * D_HEAD];
__device__ float g_ctx[MTOT * D_MODEL];                   // [b,s,h*d]

// ---------------- tf32 helpers ---------------------------------------------
__device__ __forceinline__ unsigned f32_to_tf32(float x) {
    unsigned u;
    asm("cvt.rna.tf32.f32 %0, %1;" : "=r"(u) : "f"(x));
    return u;
}
__device__ __forceinline__ void split_tf32(float x, unsigned& hi, unsigned& lo) {
    hi = f32_to_tf32(x);
    lo = f32_to_tf32(x - __uint_as_float(hi));
}
// split a float4 and store hi/lo float4s (tf32 bit patterns) to smem
__device__ __forceinline__ void split_store4(float4 v, float* hi, float* lo) {
    unsigned h0, l0, h1, l1, h2, l2, h3, l3;
    split_tf32(v.x, h0, l0); split_tf32(v.y, h1, l1);
    split_tf32(v.z, h2, l2); split_tf32(v.w, h3, l3);
    *(float4*)hi = make_float4(__uint_as_float(h0), __uint_as_float(h1),
                               __uint_as_float(h2), __uint_as_float(h3));
    *(float4*)lo = make_float4(__uint_as_float(l0), __uint_as_float(l1),
                               __uint_as_float(l2), __uint_as_float(l3));
}
// D += A(16x8) * B(8x8); A row-major frags, B col-major frags, fp32 accum.
__device__ __forceinline__ void mma8(float* c, const unsigned* a, unsigned b0, unsigned b1) {
    asm volatile(
        "mma.sync.aligned.m16n8k8.row.col.f32.tf32.tf32.f32 "
        "{%0,%1,%2,%3}, {%4,%5,%6,%7}, {%8,%9}, {%0,%1,%2,%3};"
        : "+f"(c[0]), "+f"(c[1]), "+f"(c[2]), "+f"(c[3])
        : "r"(a[0]), "r"(a[1]), "r"(a[2]), "r"(a[3]), "r"(b0), "r"(b1));
}

// ---------------- 3xTF32 GEMM: C[m,n] = sum_k A[m,k] * W[n,k] ---------------
// Block tile 128x128, BK=16, 256 threads = 8 warps (4m x 2n), warp tile 32x64.
// Pre-split hi/lo tiles in smem; mainloop is pure LDS + HMMA.
#define SSTR 20   // 16 + 4 pad: frag loads conflict-free (g*20 mod 32 distinct)

__device__ __forceinline__ void gemm3_body(const float* __restrict__ A,
                                           const float* __restrict__ W,
                                           int m0, int n0,
                                           float (&c)[2][8][4],
                                           float* sm)
{
    float* Ah = sm;                    // 128*20
    float* Al = sm + 128 * SSTR;
    float* Bh = sm + 2 * 128 * SSTR;
    float* Bl = sm + 3 * 128 * SSTR;

    const int tid  = threadIdx.x;
    const int lane = tid & 31;
    const int g    = lane >> 2;
    const int t    = lane & 3;
    const int warp = tid >> 5;
    const int wm   = (warp >> 1) * 32;
    const int wn   = (warp & 1) * 64;

    // loader: 128x16 tile = 512 float4, 2 per thread per operand
    int rowL[2], colL[2];
    #pragma unroll
    for (int u = 0; u < 2; u++) {
        int idx = tid + 256 * u;
        rowL[u] = idx >> 2;
        colL[u] = (idx & 3) * 4;
    }

    float4 pa[2], pb[2];
    #pragma unroll
    for (int u = 0; u < 2; u++) {
        pa[u] = *(const float4*)&A[(size_t)(m0 + rowL[u]) * D_MODEL + colL[u]];
        pb[u] = *(const float4*)&W[(size_t)(n0 + rowL[u]) * D_MODEL + colL[u]];
    }

    for (int k0 = 0; k0 < D_MODEL; k0 += 16) {
        #pragma unroll
        for (int u = 0; u < 2; u++) {
            const int off = rowL[u] * SSTR + colL[u];
            split_store4(pa[u], &Ah[off], &Al[off]);
            split_store4(pb[u], &Bh[off], &Bl[off]);
        }
        __syncthreads();

        if (k0 + 16 < D_MODEL) {
            #pragma unroll
            for (int u = 0; u < 2; u++) {
                pa[u] = *(const float4*)&A[(size_t)(m0 + rowL[u]) * D_MODEL + k0 + 16 + colL[u]];
                pb[u] = *(const float4*)&W[(size_t)(n0 + rowL[u]) * D_MODEL + k0 + 16 + colL[u]];
            }
        }

        #pragma unroll
        for (int ks = 0; ks < 2; ks++) {
            const int k = ks * 8;
            unsigned ahi[2][4], alo[2][4];
            #pragma unroll
            for (int i = 0; i < 2; i++) {
                const int base = (wm + 16 * i + g) * SSTR + k + t;
                ahi[i][0] = __float_as_uint(Ah[base]);
                ahi[i][1] = __float_as_uint(Ah[base + 8 * SSTR]);
                ahi[i][2] = __float_as_uint(Ah[base + 4]);
                ahi[i][3] = __float_as_uint(Ah[base + 8 * SSTR + 4]);
                alo[i][0] = __float_as_uint(Al[base]);
                alo[i][1] = __float_as_uint(Al[base + 8 * SSTR]);
                alo[i][2] = __float_as_uint(Al[base + 4]);
                alo[i][3] = __float_as_uint(Al[base + 8 * SSTR + 4]);
            }
            #pragma unroll
            for (int j = 0; j < 8; j++) {
                const int bb = (wn + 8 * j + g) * SSTR + k + t;
                const unsigned bh0 = __float_as_uint(Bh[bb]);
                const unsigned bh1 = __float_as_uint(Bh[bb + 4]);
                const unsigned bl0 = __float_as_uint(Bl[bb]);
                const unsigned bl1 = __float_as_uint(Bl[bb + 4]);
                mma8(c[0][j], ahi[0], bh0, bh1);
                mma8(c[1][j], ahi[1], bh0, bh1);
                mma8(c[0][j], alo[0], bh0, bh1);
                mma8(c[1][j], alo[1], bh0, bh1);
                mma8(c[0][j], ahi[0], bl0, bl1);
                mma8(c[1][j], ahi[1], bl0, bl1);
            }
        }
        __syncthreads();
    }
}

// Fused QKV projection; blockIdx.z selects weight. Output [b,h,s,d].
__global__ __launch_bounds__(256, 2) void gemm_qkv(const float* __restrict__ x,
                                                   const float* __restrict__ Qw,
                                                   const float* __restrict__ Kw,
                                                   const float* __restrict__ Vw)
{
    __shared__ float sm[4 * 128 * SSTR];
    float c[2][8][4];
    #pragma unroll
    for (int i = 0; i < 2; i++)
        #pragma unroll
        for (int j = 0; j < 8; j++)
            #pragma unroll
            for (int q = 0; q < 4; q++) c[i][j][q] = 0.f;

    const int m0 = blockIdx.y * 128;
    const int n0 = blockIdx.x * 128;
    const int z  = blockIdx.z;
    const float* W = (z == 0) ? Qw : (z == 1) ? Kw : Vw;

    gemm3_body(x, W, m0, n0, c, sm);

    float* dst = (z == 0) ? g_q : (z == 1) ? g_k : g_v;
    const int lane = threadIdx.x & 31;
    const int g = lane >> 2, t = lane & 3;
    const int warp = threadIdx.x >> 5;
    const int wm = (warp >> 1) * 32, wn = (warp & 1) * 64;

    #pragma unroll
    for (int i = 0; i < 2; i++) {
        #pragma unroll
        for (int j = 0; j < 8; j++) {
            const int n = n0 + wn + 8 * j + 2 * t;
            const int h = n >> 6, d = n & 63;
            const int r0 = m0 + wm + 16 * i + g;
            const int r1 = r0 + 8;
            const int b0 = r0 >> 11, s0 = r0 & 2047;
            const int b1 = r1 >> 11, s1 = r1 & 2047;
            *(float2*)&dst[((size_t)(b0 * NUM_HEADS + h) * SEQ + s0) * D_HEAD + d] =
                make_float2(c[i][j][0], c[i][j][1]);
            *(float2*)&dst[((size_t)(b1 * NUM_HEADS + h) * SEQ + s1) * D_HEAD + d] =
                make_float2(c[i][j][2], c[i][j][3]);
        }
    }
}

// Output projection: out = ctx @ Ow^T, row-major [MTOT, D_MODEL].
__global__ __launch_bounds__(256, 2) void gemm_out(const float* __restrict__ Ow,
                                                   float* __restrict__ out)
{
    __shared__ float sm[4 * 128 * SSTR];
    float c[2][8][4];
    #pragma unroll
    for (int i = 0; i < 2; i++)
        #pragma unroll
        for (int j = 0; j < 8; j++)
            #pragma unroll
            for (int q = 0; q < 4; q++) c[i][j][q] = 0.f;

    const int m0 = blockIdx.y * 128;
    const int n0 = blockIdx.x * 128;

    gemm3_body(g_ctx, Ow, m0, n0, c, sm);

    const int lane = threadIdx.x & 31;
    const int g = lane >> 2, t = lane & 3;
    const int warp = threadIdx.x >> 5;
    const int wm = (warp >> 1) * 32, wn = (warp & 1) * 64;

    #pragma unroll
    for (int i = 0; i < 2; i++) {
        #pragma unroll
        for (int j = 0; j < 8; j++) {
            const int n  = n0 + wn + 8 * j + 2 * t;
            const int r0 = m0 + wm + 16 * i + g;
            *(float2*)&out[(size_t)r0 * D_MODEL + n] = make_float2(c[i][j][0], c[i][j][1]);
            *(float2*)&out[(size_t)(r0 + 8) * D_MODEL + n] = make_float2(c[i][j][2], c[i][j][3]);
        }
    }
}

// ---------------- Flash attention with 3xTF32 mma, pre-split smem -----------
// Block = (b, h, 128-q-tile). 256 threads = 8 warps; warp w owns q rows
// [16w, 16w+16) of the tile. KV tiles of 64.
#define QSTR 68   // 64 + 4: conflict-free A/B frag loads (g*68 mod 32 = 4g)
#define VSTR 72   // 64 + 8: conflict-free col-operand loads (t*72+g distinct)

// float offsets
#define OFF_QH 0
#define OFF_QL (128 * QSTR)
#define OFF_KH (2 * 128 * QSTR)
#define OFF_KL (OFF_KH + 64 * QSTR)
#define OFF_VH (OFF_KL + 64 * QSTR)
#define OFF_VL (OFF_VH + 64 * VSTR)
#define OFF_PH (OFF_VL + 64 * VSTR)
#define OFF_PL (OFF_PH + 128 * QSTR)
#define ATTN_SMEM ((OFF_PL + 128 * QSTR) * 4)   // 210944 bytes

__global__ __launch_bounds__(256) void attn_mma(const unsigned char* __restrict__ pm)
{
    extern __shared__ float smf[];
    float* Qh = smf + OFF_QH;
    float* Ql = smf + OFF_QL;
    float* Kh = smf + OFF_KH;
    float* Kl = smf + OFF_KL;
    float* Vh = smf + OFF_VH;
    float* Vl = smf + OFF_VL;
    float* Ph = smf + OFF_PH;
    float* Pl = smf + OFF_PL;

    const int qt = gridDim.x - 1 - blockIdx.x;   // heavy blocks first
    const int h  = blockIdx.y;
    const int b  = blockIdx.z;
    const int tid  = threadIdx.x;
    const int lane = tid & 31;
    const int warp = tid >> 5;
    const int g = lane >> 2, t = lane & 3;
    const size_t base = (size_t)(b * NUM_HEADS + h) * SEQ;

    // ---- load + pre-split Q tile [128][64] ----
    #pragma unroll
    for (int u = 0; u < 8; u++) {
        const int idx = tid + 256 * u;          // 2048 float4
        const int row = idx >> 4;
        const int c4  = (idx & 15) * 4;
        float4 v = *(const float4*)&g_q[(base + (size_t)qt * 128 + row) * D_HEAD + c4];
        const int off = row * QSTR + c4;
        split_store4(v, &Qh[off], &Ql[off]);
    }

    float o[8][4];
    float m_i[2] = {-1e30f, -1e30f};
    float l_i[2] = {0.f, 0.f};
    #pragma unroll
    for (int j = 0; j < 8; j++)
        #pragma unroll
        for (int q = 0; q < 4; q++) o[j][q] = 0.f;

    const int rw = warp * 16;                    // warp's local q-row base
    const int Rg = qt * 128 + rw;                // global q-row base
    const int kt_max = 2 * qt + 1;

    for (int kt = 0; kt <= kt_max; kt++) {
        __syncthreads();   // prior readers of K/V done; Q visible on iter 0

        // ---- load + pre-split K and V tiles [64][64] ----
        #pragma unroll
        for (int u = 0; u < 4; u++) {
            const int idx = tid + 256 * u;       // 1024 float4 per tile
            const int row = idx >> 4;
            const int c4  = (idx & 15) * 4;
            const size_t grow = base + (size_t)kt * 64 + row;
            float4 kv = *(const float4*)&g_k[grow * D_HEAD + c4];
            float4 vv = *(const float4*)&g_v[grow * D_HEAD + c4];
            const int koff = row * QSTR + c4;
            const int voff = row * VSTR + c4;
            split_store4(kv, &Kh[koff], &Kl[koff]);
            split_store4(vv, &Vh[voff], &Vl[voff]);
        }
        __syncthreads();

        const int C0 = kt * 64;                  // global col base
        if (C0 > Rg + 15) continue;              // strip fully masked (causal)

        // ---- S = Q @ K^T (3xTF32) ----
        float s[8][4];
        #pragma unroll
        for (int j = 0; j < 8; j++)
            #pragma unroll
            for (int q = 0; q < 4; q++) s[j][q] = 0.f;

        #pragma unroll
        for (int ks = 0; ks < 8; ks++) {
            const int k = ks * 8;
            const int abase = (rw + g) * QSTR + k + t;
            unsigned ahi[4], alo[4];
            ahi[0] = __float_as_uint(Qh[abase]);
            ahi[1] = __float_as_uint(Qh[abase + 8 * QSTR]);
            ahi[2] = __float_as_uint(Qh[abase + 4]);
            ahi[3] = __float_as_uint(Qh[abase + 8 * QSTR + 4]);
            alo[0] = __float_as_uint(Ql[abase]);
            alo[1] = __float_as_uint(Ql[abase + 8 * QSTR]);
            alo[2] = __float_as_uint(Ql[abase + 4]);
            alo[3] = __float_as_uint(Ql[abase + 8 * QSTR + 4]);
            #pragma unroll
            for (int j = 0; j < 8; j++) {
                const int bb = (8 * j + g) * QSTR + k + t;
                const unsigned bh0 = __float_as_uint(Kh[bb]);
                const unsigned bh1 = __float_as_uint(Kh[bb + 4]);
                const unsigned bl0 = __float_as_uint(Kl[bb]);
                const unsigned bl1 = __float_as_uint(Kl[bb + 4]);
                mma8(s[j], ahi, bh0, bh1);
                mma8(s[j], alo, bh0, bh1);
                mma8(s[j], ahi, bl0, bl1);
            }
        }

        // ---- scale + causal + padding masks ----
        const unsigned char* pmb = pm + (size_t)b * SEQ + C0;
        const int r0 = Rg + g, r1 = r0 + 8;      // global q rows
        #pragma unroll
        for (int j = 0; j < 8; j++) {
            const int c0 = C0 + 8 * j + 2 * t, c1 = c0 + 1;
            const bool p0 = pmb[8 * j + 2 * t] != 0;
            const bool p1 = pmb[8 * j + 2 * t + 1] != 0;
            float v;
            v = s[j][0] * 0.125f; if (c0 > r0 || p0) v = -1e30f; s[j][0] = v;
            v = s[j][1] * 0.125f; if (c1 > r0 || p1) v = -1e30f; s[j][1] = v;
            v = s[j][2] * 0.125f; if (c0 > r1 || p0) v = -1e30f; s[j][2] = v;
            v = s[j][3] * 0.125f; if (c1 > r1 || p1) v = -1e30f; s[j][3] = v;
        }

        // ---- online softmax (rows r0, r1; reduce over quad lanes) ----
        #pragma unroll
        for (int rr = 0; rr < 2; rr++) {
            float rm = -1e30f;
            #pragma unroll
            for (int j = 0; j < 8; j++)
                rm = fmaxf(rm, fmaxf(s[j][2 * rr], s[j][2 * rr + 1]));
            rm = fmaxf(rm, __shfl_xor_sync(0xffffffffu, rm, 1));
            rm = fmaxf(rm, __shfl_xor_sync(0xffffffffu, rm, 2));
            const float mn    = fmaxf(m_i[rr], rm);
            const float alpha = __expf(m_i[rr] - mn);
            m_i[rr] = mn;
            float rs = 0.f;
            #pragma unroll
            for (int j = 0; j < 8; j++) {
                s[j][2 * rr    ] = __expf(s[j][2 * rr    ] - mn);
                s[j][2 * rr + 1] = __expf(s[j][2 * rr + 1] - mn);
                rs += s[j][2 * rr] + s[j][2 * rr + 1];
            }
            rs += __shfl_xor_sync(0xffffffffu, rs, 1);
            rs += __shfl_xor_sync(0xffffffffu, rs, 2);
            l_i[rr] = l_i[rr] * alpha + rs;
            #pragma unroll
            for (int j = 0; j < 8; j++) {
                o[j][2 * rr    ] *= alpha;
                o[j][2 * rr + 1] *= alpha;
            }
        }

        // ---- split-write P (warp-private rows; only __syncwarp needed) ----
        #pragma unroll
        for (int j = 0; j < 8; j++) {
            unsigned h0, l0, h1, l1, h2, l2, h3, l3;
            split_tf32(s[j][0], h0, l0); split_tf32(s[j][1], h1, l1);
            split_tf32(s[j][2], h2, l2); split_tf32(s[j][3], h3, l3);
            const int p0 = (rw + g) * QSTR + 8 * j + 2 * t;
            const int p1 = p0 + 8 * QSTR;
            *(float2*)&Ph[p0] = make_float2(__uint_as_float(h0), __uint_as_float(h1));
            *(float2*)&Pl[p0] = make_float2(__uint_as_float(l0), __uint_as_float(l1));
            *(float2*)&Ph[p1] = make_float2(__uint_as_float(h2), __uint_as_float(h3));
            *(float2*)&Pl[p1] = make_float2(__uint_as_float(l2), __uint_as_float(l3));
        }
        __syncwarp();

        // ---- O += P @ V (3xTF32); V row-major is the .col B operand ----
        #pragma unroll
        for (int cc = 0; cc < 8; cc++) {
            const int kk = cc * 8;
            const int abase = (rw + g) * QSTR + kk + t;
            unsigned ahi[4], alo[4];
            ahi[0] = __float_as_uint(Ph[abase]);
            ahi[1] = __float_as_uint(Ph[abase + 8 * QSTR]);
            ahi[2] = __float_as_uint(Ph[abase + 4]);
            ahi[3] = __float_as_uint(Ph[abase + 8 * QSTR + 4]);
            alo[0] = __float_as_uint(Pl[abase]);
            alo[1] = __float_as_uint(Pl[abase + 8 * QSTR]);
            alo[2] = __float_as_uint(Pl[abase + 4]);
            alo[3] = __float_as_uint(Pl[abase + 8 * QSTR + 4]);
            #pragma unroll
            for (int j = 0; j < 8; j++) {
                const int b0i = (kk + t) * VSTR + 8 * j + g;
                const int b1i = (kk + t + 4) * VSTR + 8 * j + g;
                const unsigned bh0 = __float_as_uint(Vh[b0i]);
                const unsigned bh1 = __float_as_uint(Vh[b1i]);
                const unsigned bl0 = __float_as_uint(Vl[b0i]);
                const unsigned bl1 = __float_as_uint(Vl[b1i]);
                mma8(o[j], ahi, bh0, bh1);
                mma8(o[j], alo, bh0, bh1);
                mma8(o[j], ahi, bl0, bl1);
            }
        }
    }

    // ---- normalize + write ctx [b, s, h*64 + col] ----
    const float inv0 = 1.f / l_i[0];
    const float inv1 = 1.f / l_i[1];
    const int row0 = qt * 128 + rw + g;
    float* d0 = g_ctx + ((size_t)b * SEQ + row0    ) * D_MODEL + h * D_HEAD;
    float* d1 = g_ctx + ((size_t)b * SEQ + row0 + 8) * D_MODEL + h * D_HEAD;
    #pragma unroll
    for (int j = 0; j < 8; j++) {
        const int cidx = 8 * j + 2 * t;
        *(float2*)&d0[cidx] = make_float2(o[j][0] * inv0, o[j][1] * inv0);
        *(float2*)&d1[cidx] = make_float2(o[j][2] * inv1, o[j][3] * inv1);
    }
}

// ---------------- launch ----------------------------------------------------
extern "C" void kernel_launch(void* const* d_in, const int* in_sizes, int n_in,
                              void* d_out, int out_size)
{
    (void)in_sizes; (void)n_in; (void)out_size;
    const float* x  = (const float*)d_in[0];
    const float* Qw = (const float*)d_in[1];
    const float* Kw = (const float*)d_in[2];
    const float* Vw = (const float*)d_in[3];
    const float* Ow = (const float*)d_in[4];
    const unsigned char* pm = (const unsigned char*)d_in[5];
    float* out = (float*)d_out;

    cudaFuncSetAttribute(attn_mma,
                         cudaFuncAttributeMaxDynamicSharedMemorySize,
                         ATTN_SMEM);

    dim3 gq(D_MODEL / 128, MTOT / 128, 3);        // 8 x 64 x 3
    gemm_qkv<<<gq, 256>>>(x, Qw, Kw, Vw);

    dim3 ga(SEQ / 128, NUM_HEADS, BATCH);         // 16 x 16 x 4
    attn_mma<<<ga, 256, ATTN_SMEM>>>(pm);

    dim3 go(D_MODEL / 128, MTOT / 128);           // 8 x 64
    gemm_out<<<go, 256>>>(Ow, out);
}

// round 4
// speedup vs baseline: 3.5682x; 1.6731x over previous
#include <cuda_runtime.h>
#include <cuda_bf16.h>
#include <cstdint>

#define D_MODEL   1024
#define NUM_HEADS 16
#define D_HEAD    64
#define BATCH     4
#define SEQ       2048
#define MTOT      (BATCH * SEQ)   // 8192

// ---------------- scratch (device globals: allocation-guard safe) ----------
__device__ float g_q[BATCH * NUM_HEADS * SEQ * D_HEAD];   // [b,h,s,d]
__device__ float g_k[BATCH * NUM_HEADS * SEQ * D_HEAD];
__device__ float g_v[BATCH * NUM_HEADS * SEQ * D_HEAD];
__device__ float g_ctx[MTOT * D_MODEL];                   // [b,s,h*d]

// ---------------- bf16 split helpers ----------------------------------------
__device__ __forceinline__ void split_bf(float x, __nv_bfloat16& h, __nv_bfloat16& l) {
    h = __float2bfloat16(x);
    l = __float2bfloat16(x - __bfloat162float(h));
}
__device__ __forceinline__ unsigned pk(__nv_bfloat16 a, __nv_bfloat16 b) {
    return (unsigned)__bfloat16_as_ushort(a) | ((unsigned)__bfloat16_as_ushort(b) << 16);
}
// split a float4 into 4 consecutive bf16 hi + 4 lo (8-byte stores)
__device__ __forceinline__ void split_store4(float4 v, __nv_bfloat16* hp, __nv_bfloat16* lp) {
    __nv_bfloat16 h0, l0, h1, l1, h2, l2, h3, l3;
    split_bf(v.x, h0, l0); split_bf(v.y, h1, l1);
    split_bf(v.z, h2, l2); split_bf(v.w, h3, l3);
    *(uint2*)hp = make_uint2(pk(h0, h1), pk(h2, h3));
    *(uint2*)lp = make_uint2(pk(l0, l1), pk(l2, l3));
}
__device__ __forceinline__ unsigned ld2u(const __nv_bfloat16* p) {
    return *(const unsigned*)p;
}
// D += A(16x16) * B(16x8); bf16 in, fp32 accum
__device__ __forceinline__ void mma16(float* c, const unsigned* a, unsigned b0, unsigned b1) {
    asm volatile(
        "mma.sync.aligned.m16n8k16.row.col.f32.bf16.bf16.f32 "
        "{%0,%1,%2,%3}, {%4,%5,%6,%7}, {%8,%9}, {%0,%1,%2,%3};"
        : "+f"(c[0]), "+f"(c[1]), "+f"(c[2]), "+f"(c[3])
        : "r"(a[0]), "r"(a[1]), "r"(a[2]), "r"(a[3]), "r"(b0), "r"(b1));
}

// ---------------- fast exp2 on the FMA pipe (MUFU-free) ---------------------
__device__ __forceinline__ float exp2_fast(float y) {
    y = fmaxf(y, -120.f);                       // masked (-1e30) -> ~0
    float z = y + 12582912.f;                   // round-to-nearest int, |y| < 2^21
    int   e = __float_as_int(z);                // low bits hold the integer
    float f = y - (z - 12582912.f);             // f in [-0.5, 0.5]
    float p = 1.f + f * (0.6931471805599453f + f * (0.2402265069591007f +
              f * (0.0555041086648216f + f * (0.0096181291076285f +
              f * 0.0013333558146429f))));
    return __int_as_float(__float_as_int(p) + (e << 23));
}
#define SCALE_LOG2E 0.18033688011112042f   // 0.125 * log2(e)

// ---------------- split-bf16 GEMM: C[m,n] = sum_k A[m,k] * W[n,k] -----------
// Block tile 128x128, BK=16 (one m16n8k16 k-step), 256 threads = 8 warps
// (4m x 2n), warp tile 32x64. Pre-split hi/lo bf16 tiles in smem.
#define SSTR 24   // 16 + 8 pad (bf16): frag loads conflict-free

__device__ __forceinline__ void gemm3_body(const float* __restrict__ A,
                                           const float* __restrict__ W,
                                           int m0, int n0,
                                           float (&c)[2][8][4],
                                           __nv_bfloat16* sm)
{
    __nv_bfloat16* Ah = sm;                     // 128*24 each
    __nv_bfloat16* Al = sm + 128 * SSTR;
    __nv_bfloat16* Bh = sm + 2 * 128 * SSTR;
    __nv_bfloat16* Bl = sm + 3 * 128 * SSTR;

    const int tid  = threadIdx.x;
    const int lane = tid & 31;
    const int g    = lane >> 2;
    const int t    = lane & 3;
    const int warp = tid >> 5;
    const int wm   = (warp >> 1) * 32;
    const int wn   = (warp & 1) * 64;

    // loader: 128x16 floats = 512 float4, 2 per thread per operand
    int rowL[2], colL[2];
    #pragma unroll
    for (int u = 0; u < 2; u++) {
        int idx = tid + 256 * u;
        rowL[u] = idx >> 2;
        colL[u] = (idx & 3) * 4;
    }

    float4 pa[2], pb[2];
    #pragma unroll
    for (int u = 0; u < 2; u++) {
        pa[u] = *(const float4*)&A[(size_t)(m0 + rowL[u]) * D_MODEL + colL[u]];
        pb[u] = *(const float4*)&W[(size_t)(n0 + rowL[u]) * D_MODEL + colL[u]];
    }

    for (int k0 = 0; k0 < D_MODEL; k0 += 16) {
        #pragma unroll
        for (int u = 0; u < 2; u++) {
            const int off = rowL[u] * SSTR + colL[u];
            split_store4(pa[u], &Ah[off], &Al[off]);
            split_store4(pb[u], &Bh[off], &Bl[off]);
        }
        __syncthreads();

        if (k0 + 16 < D_MODEL) {
            #pragma unroll
            for (int u = 0; u < 2; u++) {
                pa[u] = *(const float4*)&A[(size_t)(m0 + rowL[u]) * D_MODEL + k0 + 16 + colL[u]];
                pb[u] = *(const float4*)&W[(size_t)(n0 + rowL[u]) * D_MODEL + k0 + 16 + colL[u]];
            }
        }

        unsigned ahi[2][4], alo[2][4];
        #pragma unroll
        for (int i = 0; i < 2; i++) {
            const int base = (wm + 16 * i + g) * SSTR + 2 * t;
            ahi[i][0] = ld2u(&Ah[base]);
            ahi[i][1] = ld2u(&Ah[base + 8 * SSTR]);
            ahi[i][2] = ld2u(&Ah[base + 8]);
            ahi[i][3] = ld2u(&Ah[base + 8 * SSTR + 8]);
            alo[i][0] = ld2u(&Al[base]);
            alo[i][1] = ld2u(&Al[base + 8 * SSTR]);
            alo[i][2] = ld2u(&Al[base + 8]);
            alo[i][3] = ld2u(&Al[base + 8 * SSTR + 8]);
        }
        #pragma unroll
        for (int j = 0; j < 8; j++) {
            const int bb = (wn + 8 * j + g) * SSTR + 2 * t;
            const unsigned bh0 = ld2u(&Bh[bb]);
            const unsigned bh1 = ld2u(&Bh[bb + 8]);
            const unsigned bl0 = ld2u(&Bl[bb]);
            const unsigned bl1 = ld2u(&Bl[bb + 8]);
            mma16(c[0][j], ahi[0], bh0, bh1);
            mma16(c[1][j], ahi[1], bh0, bh1);
            mma16(c[0][j], alo[0], bh0, bh1);
            mma16(c[1][j], alo[1], bh0, bh1);
            mma16(c[0][j], ahi[0], bl0, bl1);
            mma16(c[1][j], ahi[1], bl0, bl1);
        }
        __syncthreads();
    }
}

// Fused QKV projection; blockIdx.z selects weight. Output [b,h,s,d].
__global__ __launch_bounds__(256, 2) void gemm_qkv(const float* __restrict__ x,
                                                   const float* __restrict__ Qw,
                                                   const float* __restrict__ Kw,
                                                   const float* __restrict__ Vw)
{
    __shared__ __nv_bfloat16 sm[4 * 128 * SSTR];
    float c[2][8][4];
    #pragma unroll
    for (int i = 0; i < 2; i++)
        #pragma unroll
        for (int j = 0; j < 8; j++)
            #pragma unroll
            for (int q = 0; q < 4; q++) c[i][j][q] = 0.f;

    const int m0 = blockIdx.y * 128;
    const int n0 = blockIdx.x * 128;
    const int z  = blockIdx.z;
    const float* W = (z == 0) ? Qw : (z == 1) ? Kw : Vw;

    gemm3_body(x, W, m0, n0, c, sm);

    float* dst = (z == 0) ? g_q : (z == 1) ? g_k : g_v;
    const int lane = threadIdx.x & 31;
    const int g = lane >> 2, t = lane & 3;
    const int warp = threadIdx.x >> 5;
    const int wm = (warp >> 1) * 32, wn = (warp & 1) * 64;

    #pragma unroll
    for (int i = 0; i < 2; i++) {
        #pragma unroll
        for (int j = 0; j < 8; j++) {
            const int n = n0 + wn + 8 * j + 2 * t;
            const int h = n >> 6, d = n & 63;
            const int r0 = m0 + wm + 16 * i + g;
            const int r1 = r0 + 8;
            const int b0 = r0 >> 11, s0 = r0 & 2047;
            const int b1 = r1 >> 11, s1 = r1 & 2047;
            *(float2*)&dst[((size_t)(b0 * NUM_HEADS + h) * SEQ + s0) * D_HEAD + d] =
                make_float2(c[i][j][0], c[i][j][1]);
            *(float2*)&dst[((size_t)(b1 * NUM_HEADS + h) * SEQ + s1) * D_HEAD + d] =
                make_float2(c[i][j][2], c[i][j][3]);
        }
    }
}

// Output projection: out = ctx @ Ow^T, row-major [MTOT, D_MODEL].
__global__ __launch_bounds__(256, 2) void gemm_out(const float* __restrict__ Ow,
                                                   float* __restrict__ out)
{
    __shared__ __nv_bfloat16 sm[4 * 128 * SSTR];
    float c[2][8][4];
    #pragma unroll
    for (int i = 0; i < 2; i++)
        #pragma unroll
        for (int j = 0; j < 8; j++)
            #pragma unroll
            for (int q = 0; q < 4; q++) c[i][j][q] = 0.f;

    const int m0 = blockIdx.y * 128;
    const int n0 = blockIdx.x * 128;

    gemm3_body(g_ctx, Ow, m0, n0, c, sm);

    const int lane = threadIdx.x & 31;
    const int g = lane >> 2, t = lane & 3;
    const int warp = threadIdx.x >> 5;
    const int wm = (warp >> 1) * 32, wn = (warp & 1) * 64;

    #pragma unroll
    for (int i = 0; i < 2; i++) {
        #pragma unroll
        for (int j = 0; j < 8; j++) {
            const int n  = n0 + wn + 8 * j + 2 * t;
            const int r0 = m0 + wm + 16 * i + g;
            *(float2*)&out[(size_t)r0 * D_MODEL + n] = make_float2(c[i][j][0], c[i][j][1]);
            *(float2*)&out[(size_t)(r0 + 8) * D_MODEL + n] = make_float2(c[i][j][2], c[i][j][3]);
        }
    }
}

// ---------------- Flash attention: split-bf16 mma + FMA-pipe exp2 -----------
// Block = (b, h, 128-q-tile). 256 threads = 8 warps; warp w owns q rows
// [16w, 16w+16). KV tiles of 64. V stored transposed for vector B-frag loads.
#define QSTR  72   // bf16 stride (64+8): conflict-free frag loads
#define VTSTR 74   // transposed-V stride: conflict-free-ish

// element offsets in bf16 units
#define OFF_QH 0
#define OFF_QL (128 * QSTR)
#define OFF_KH (2 * 128 * QSTR)
#define OFF_KL (OFF_KH + 64 * QSTR)
#define OFF_VH (OFF_KL + 64 * QSTR)
#define OFF_VL (OFF_VH + 64 * VTSTR)
#define OFF_PH (OFF_VL + 64 * VTSTR)
#define OFF_PL (OFF_PH + 128 * QSTR)
#define ATTN_SMEM ((OFF_PL + 128 * QSTR) * 2)   // bytes = 111104

__global__ __launch_bounds__(256, 2) void attn_mma(const unsigned char* __restrict__ pm)
{
    extern __shared__ __nv_bfloat16 smb[];
    __nv_bfloat16* Qh  = smb + OFF_QH;
    __nv_bfloat16* Ql  = smb + OFF_QL;
    __nv_bfloat16* Kh  = smb + OFF_KH;
    __nv_bfloat16* Kl  = smb + OFF_KL;
    __nv_bfloat16* Vth = smb + OFF_VH;   // [dv][c]
    __nv_bfloat16* Vtl = smb + OFF_VL;
    __nv_bfloat16* Ph  = smb + OFF_PH;
    __nv_bfloat16* Pl  = smb + OFF_PL;

    const int qt = gridDim.x - 1 - blockIdx.x;   // heavy blocks first
    const int h  = blockIdx.y;
    const int b  = blockIdx.z;
    const int tid  = threadIdx.x;
    const int lane = tid & 31;
    const int warp = tid >> 5;
    const int g = lane >> 2, t = lane & 3;
    const size_t base = (size_t)(b * NUM_HEADS + h) * SEQ;

    // ---- load + split Q tile [128][64] ----
    #pragma unroll
    for (int u = 0; u < 8; u++) {
        const int idx = tid + 256 * u;          // 2048 float4
        const int row = idx >> 4;
        const int c4  = (idx & 15) * 4;
        float4 v = *(const float4*)&g_q[(base + (size_t)qt * 128 + row) * D_HEAD + c4];
        const int off = row * QSTR + c4;
        split_store4(v, &Qh[off], &Ql[off]);
    }

    float o[8][4];
    float m_i[2] = {-1e30f, -1e30f};
    float l_i[2] = {0.f, 0.f};
    #pragma unroll
    for (int j = 0; j < 8; j++)
        #pragma unroll
        for (int q = 0; q < 4; q++) o[j][q] = 0.f;

    const int rw = warp * 16;                    // warp's local q-row base
    const int Rg = qt * 128 + rw;                // global q-row base
    const int kt_max = 2 * qt + 1;

    for (int kt = 0; kt <= kt_max; kt++) {
        __syncthreads();   // prior readers of K/V done; Q visible on iter 0

        // ---- load + split K tile; transpose-split V tile ----
        #pragma unroll
        for (int u = 0; u < 4; u++) {
            const int idx = tid + 256 * u;       // 1024 float4 per tile
            const int row = idx >> 4;
            const int c4  = (idx & 15) * 4;
            const size_t grow = base + (size_t)kt * 64 + row;
            float4 kv = *(const float4*)&g_k[grow * D_HEAD + c4];
            float4 vv = *(const float4*)&g_v[grow * D_HEAD + c4];
            const int koff = row * QSTR + c4;
            split_store4(kv, &Kh[koff], &Kl[koff]);
            __nv_bfloat16 vh, vl;
            split_bf(vv.x, vh, vl); Vth[(c4    ) * VTSTR + row] = vh; Vtl[(c4    ) * VTSTR + row] = vl;
            split_bf(vv.y, vh, vl); Vth[(c4 + 1) * VTSTR + row] = vh; Vtl[(c4 + 1) * VTSTR + row] = vl;
            split_bf(vv.z, vh, vl); Vth[(c4 + 2) * VTSTR + row] = vh; Vtl[(c4 + 2) * VTSTR + row] = vl;
            split_bf(vv.w, vh, vl); Vth[(c4 + 3) * VTSTR + row] = vh; Vtl[(c4 + 3) * VTSTR + row] = vl;
        }
        __syncthreads();

        const int C0 = kt * 64;                  // global col base
        if (C0 > Rg + 15) continue;              // strip fully masked (causal)

        // ---- S = Q @ K^T (split-bf16, 4 k-steps of 16) ----
        float s[8][4];
        #pragma unroll
        for (int j = 0; j < 8; j++)
            #pragma unroll
            for (int q = 0; q < 4; q++) s[j][q] = 0.f;

        #pragma unroll
        for (int ks = 0; ks < 4; ks++) {
            const int kk = ks * 16;
            const int ab = (rw + g) * QSTR + kk + 2 * t;
            unsigned ahi[4], alo[4];
            ahi[0] = ld2u(&Qh[ab]);
            ahi[1] = ld2u(&Qh[ab + 8 * QSTR]);
            ahi[2] = ld2u(&Qh[ab + 8]);
            ahi[3] = ld2u(&Qh[ab + 8 * QSTR + 8]);
            alo[0] = ld2u(&Ql[ab]);
            alo[1] = ld2u(&Ql[ab + 8 * QSTR]);
            alo[2] = ld2u(&Ql[ab + 8]);
            alo[3] = ld2u(&Ql[ab + 8 * QSTR + 8]);
            #pragma unroll
            for (int j = 0; j < 8; j++) {
                const int bb = (8 * j + g) * QSTR + kk + 2 * t;
                const unsigned bh0 = ld2u(&Kh[bb]);
                const unsigned bh1 = ld2u(&Kh[bb + 8]);
                const unsigned bl0 = ld2u(&Kl[bb]);
                const unsigned bl1 = ld2u(&Kl[bb + 8]);
                mma16(s[j], ahi, bh0, bh1);
                mma16(s[j], alo, bh0, bh1);
                mma16(s[j], ahi, bl0, bl1);
            }
        }

        // ---- scale (log2 domain) + causal + padding masks ----
        const unsigned char* pmb = pm + (size_t)b * SEQ + C0;
        const int r0 = Rg + g, r1 = r0 + 8;      // global q rows
        #pragma unroll
        for (int j = 0; j < 8; j++) {
            const int c0 = C0 + 8 * j + 2 * t, c1 = c0 + 1;
            const bool p0 = pmb[8 * j + 2 * t] != 0;
            const bool p1 = pmb[8 * j + 2 * t + 1] != 0;
            float v;
            v = s[j][0] * SCALE_LOG2E; if (c0 > r0 || p0) v = -1e30f; s[j][0] = v;
            v = s[j][1] * SCALE_LOG2E; if (c1 > r0 || p1) v = -1e30f; s[j][1] = v;
            v = s[j][2] * SCALE_LOG2E; if (c0 > r1 || p0) v = -1e30f; s[j][2] = v;
            v = s[j][3] * SCALE_LOG2E; if (c1 > r1 || p1) v = -1e30f; s[j][3] = v;
        }

        // ---- online softmax, base-2, FMA-pipe exp ----
        #pragma unroll
        for (int rr = 0; rr < 2; rr++) {
            float rm = -1e30f;
            #pragma unroll
            for (int j = 0; j < 8; j++)
                rm = fmaxf(rm, fmaxf(s[j][2 * rr], s[j][2 * rr + 1]));
            rm = fmaxf(rm, __shfl_xor_sync(0xffffffffu, rm, 1));
            rm = fmaxf(rm, __shfl_xor_sync(0xffffffffu, rm, 2));
            const float mn    = fmaxf(m_i[rr], rm);
            const float alpha = exp2_fast(m_i[rr] - mn);
            m_i[rr] = mn;
            float rs = 0.f;
            #pragma unroll
            for (int j = 0; j < 8; j++) {
                s[j][2 * rr    ] = exp2_fast(s[j][2 * rr    ] - mn);
                s[j][2 * rr + 1] = exp2_fast(s[j][2 * rr + 1] - mn);
                rs += s[j][2 * rr] + s[j][2 * rr + 1];
            }
            rs += __shfl_xor_sync(0xffffffffu, rs, 1);
            rs += __shfl_xor_sync(0xffffffffu, rs, 2);
            l_i[rr] = l_i[rr] * alpha + rs;
            #pragma unroll
            for (int j = 0; j < 8; j++) {
                o[j][2 * rr    ] *= alpha;
                o[j][2 * rr + 1] *= alpha;
            }
        }

        // ---- split-write P (warp-private rows; __syncwarp suffices) ----
        #pragma unroll
        for (int j = 0; j < 8; j++) {
            __nv_bfloat16 h0, l0, h1, l1, h2, l2, h3, l3;
            split_bf(s[j][0], h0, l0); split_bf(s[j][1], h1, l1);
            split_bf(s[j][2], h2, l2); split_bf(s[j][3], h3, l3);
            const int p0 = (rw + g) * QSTR + 8 * j + 2 * t;
            const int p1 = p0 + 8 * QSTR;
            *(unsigned*)&Ph[p0] = pk(h0, h1);
            *(unsigned*)&Pl[p0] = pk(l0, l1);
            *(unsigned*)&Ph[p1] = pk(h2, h3);
            *(unsigned*)&Pl[p1] = pk(l2, l3);
        }
        __syncwarp();

        // ---- O += P @ V (split-bf16, 4 k-steps over c) ----
        #pragma unroll
        for (int ks = 0; ks < 4; ks++) {
            const int kk = ks * 16;
            const int ab = (rw + g) * QSTR + kk + 2 * t;
            unsigned ahi[4], alo[4];
            ahi[0] = ld2u(&Ph[ab]);
            ahi[1] = ld2u(&Ph[ab + 8 * QSTR]);
            ahi[2] = ld2u(&Ph[ab + 8]);
            ahi[3] = ld2u(&Ph[ab + 8 * QSTR + 8]);
            alo[0] = ld2u(&Pl[ab]);
            alo[1] = ld2u(&Pl[ab + 8 * QSTR]);
            alo[2] = ld2u(&Pl[ab + 8]);
            alo[3] = ld2u(&Pl[ab + 8 * QSTR + 8]);
            #pragma unroll
            for (int j = 0; j < 8; j++) {
                const int bb = (8 * j + g) * VTSTR + kk + 2 * t;
                const unsigned bh0 = ld2u(&Vth[bb]);
                const unsigned bh1 = ld2u(&Vth[bb + 8]);
                const unsigned bl0 = ld2u(&Vtl[bb]);
                const unsigned bl1 = ld2u(&Vtl[bb + 8]);
                mma16(o[j], ahi, bh0, bh1);
                mma16(o[j], alo, bh0, bh1);
                mma16(o[j], ahi, bl0, bl1);
            }
        }
    }

    // ---- normalize + write ctx [b, s, h*64 + col] ----
    const float inv0 = 1.f / l_i[0];
    const float inv1 = 1.f / l_i[1];
    const int row0 = qt * 128 + rw + g;
    float* d0 = g_ctx + ((size_t)b * SEQ + row0    ) * D_MODEL + h * D_HEAD;
    float* d1 = g_ctx + ((size_t)b * SEQ + row0 + 8) * D_MODEL + h * D_HEAD;
    #pragma unroll
    for (int j = 0; j < 8; j++) {
        const int cidx = 8 * j + 2 * t;
        *(float2*)&d0[cidx] = make_float2(o[j][0] * inv0, o[j][1] * inv0);
        *(float2*)&d1[cidx] = make_float2(o[j][2] * inv1, o[j][3] * inv1);
    }
}

// ---------------- launch ----------------------------------------------------
extern "C" void kernel_launch(void* const* d_in, const int* in_sizes, int n_in,
                              void* d_out, int out_size)
{
    (void)in_sizes; (void)n_in; (void)out_size;
    const float* x  = (const float*)d_in[0];
    const float* Qw = (const float*)d_in[1];
    const float* Kw = (const float*)d_in[2];
    const float* Vw = (const float*)d_in[3];
    const float* Ow = (const float*)d_in[4];
    const unsigned char* pm = (const unsigned char*)d_in[5];
    float* out = (float*)d_out;

    cudaFuncSetAttribute(attn_mma,
                         cudaFuncAttributeMaxDynamicSharedMemorySize,
                         ATTN_SMEM);

    dim3 gq(D_MODEL / 128, MTOT / 128, 3);        // 8 x 64 x 3
    gemm_qkv<<<gq, 256>>>(x, Qw, Kw, Vw);

    dim3 ga(SEQ / 128, NUM_HEADS, BATCH);         // 16 x 16 x 4
    attn_mma<<<ga, 256, ATTN_SMEM>>>(pm);

    dim3 go(D_MODEL / 128, MTOT / 128);           // 8 x 64
    gemm_out<<<go, 256>>>(Ow, out);
}

// round 5
// speedup vs baseline: 3.7595x; 1.0536x over previous
#include <cuda_runtime.h>
#include <cuda_bf16.h>
#include <cstdint>

#define D_MODEL   1024
#define NUM_HEADS 16
#define D_HEAD    64
#define BATCH     4
#define SEQ       2048
#define MTOT      (BATCH * SEQ)   // 8192
#define QKV_EL    (BATCH * NUM_HEADS * SEQ * D_HEAD)   // 8388608

// ---------------- scratch (device globals: allocation-guard safe) ----------
__device__ __nv_bfloat16 g_xh[MTOT * D_MODEL],  g_xl[MTOT * D_MODEL];
__device__ __nv_bfloat16 g_wh[4][D_MODEL * D_MODEL], g_wl[4][D_MODEL * D_MODEL];
__device__ __nv_bfloat16 g_qh[QKV_EL], g_ql[QKV_EL];          // [b,h,s,d]
__device__ __nv_bfloat16 g_kh[QKV_EL], g_kl[QKV_EL];          // [b,h,s,d]
__device__ __nv_bfloat16 g_vth[QKV_EL], g_vtl[QKV_EL];        // [b,h,d,s] (transposed)
__device__ __nv_bfloat16 g_ch[MTOT * D_MODEL], g_cl[MTOT * D_MODEL];   // ctx split

// ---------------- helpers ----------------------------------------------------
__device__ __forceinline__ void split_bf(float x, __nv_bfloat16& h, __nv_bfloat16& l) {
    h = __float2bfloat16(x);
    l = __float2bfloat16(x - __bfloat162float(h));
}
__device__ __forceinline__ unsigned pk(__nv_bfloat16 a, __nv_bfloat16 b) {
    return (unsigned)__bfloat16_as_ushort(a) | ((unsigned)__bfloat16_as_ushort(b) << 16);
}
__device__ __forceinline__ void split_store4(float4 v, __nv_bfloat16* hp, __nv_bfloat16* lp) {
    __nv_bfloat16 h0, l0, h1, l1, h2, l2, h3, l3;
    split_bf(v.x, h0, l0); split_bf(v.y, h1, l1);
    split_bf(v.z, h2, l2); split_bf(v.w, h3, l3);
    *(uint2*)hp = make_uint2(pk(h0, h1), pk(h2, h3));
    *(uint2*)lp = make_uint2(pk(l0, l1), pk(l2, l3));
}
__device__ __forceinline__ unsigned ld2u(const __nv_bfloat16* p) {
    return *(const unsigned*)p;
}
__device__ __forceinline__ void mma16(float* c, const unsigned* a, unsigned b0, unsigned b1) {
    asm volatile(
        "mma.sync.aligned.m16n8k16.row.col.f32.bf16.bf16.f32 "
        "{%0,%1,%2,%3}, {%4,%5,%6,%7}, {%8,%9}, {%0,%1,%2,%3};"
        : "+f"(c[0]), "+f"(c[1]), "+f"(c[2]), "+f"(c[3])
        : "r"(a[0]), "r"(a[1]), "r"(a[2]), "r"(a[3]), "r"(b0), "r"(b1));
}
__device__ __forceinline__ void cp16(__nv_bfloat16* s, const __nv_bfloat16* g) {
    unsigned sa = (unsigned)__cvta_generic_to_shared(s);
    asm volatile("cp.async.cg.shared.global [%0], [%1], 16;" :: "r"(sa), "l"(g));
}
#define CP_COMMIT() asm volatile("cp.async.commit_group;")
#define CP_WAIT0()  asm volatile("cp.async.wait_group 0;")

// fast exp2 on the FMA pipe (MUFU-free)
__device__ __forceinline__ float exp2_fast(float y) {
    y = fmaxf(y, -120.f);
    float z = y + 12582912.f;
    int   e = __float_as_int(z);
    float f = y - (z - 12582912.f);
    float p = 1.f + f * (0.6931471805599453f + f * (0.2402265069591007f +
              f * (0.0555041086648216f + f * (0.0096181291076285f +
              f * 0.0013333558146429f))));
    return __int_as_float(__float_as_int(p) + (e << 23));
}
#define SCALE_LOG2E 0.18033688011112042f   // 0.125 * log2(e)

// ---------------- one-shot split of x + weights ------------------------------
// 2M float4 for x, 256K float4 per weight; flat grid.
__global__ __launch_bounds__(256) void split_all(const float* __restrict__ x,
                                                 const float* __restrict__ Qw,
                                                 const float* __restrict__ Kw,
                                                 const float* __restrict__ Vw,
                                                 const float* __restrict__ Ow)
{
    const int idx = blockIdx.x * 256 + threadIdx.x;        // one float4 each
    const float* src;
    __nv_bfloat16 *hp, *lp;
    size_t off;
    if (idx < 2097152) {
        src = x; off = idx; hp = g_xh; lp = g_xl;
    } else {
        const int w = (idx - 2097152) >> 18;
        off = (size_t)((idx - 2097152) & 262143);
        src = (w == 0) ? Qw : (w == 1) ? Kw : (w == 2) ? Vw : Ow;
        hp = g_wh[w]; lp = g_wl[w];
    }
    float4 v = ((const float4*)src)[off];
    split_store4(v, hp + off * 4, lp + off * 4);
}

// ---------------- split-bf16 GEMM, cp.async double-buffered ------------------
// Block tile 128x128, BK=32, 256 threads = 8 warps (4m x 2n), warp tile 32x64.
#define SSTR 40                       // bf16 stride (32+8): conflict-free frags
#define GBUF (128 * SSTR)             // one operand-half buffer (elements)
#define GSTG (4 * GBUF)               // one stage: Ah, Al, Bh, Bl
#define GEMM_SMEM (2 * GSTG * 2)      // bytes = 81920

__device__ __forceinline__ void gemm_bf_body(const __nv_bfloat16* __restrict__ Agh,
                                             const __nv_bfloat16* __restrict__ Agl,
                                             const __nv_bfloat16* __restrict__ Bgh,
                                             const __nv_bfloat16* __restrict__ Bgl,
                                             int m0, int n0,
                                             float (&c)[2][8][4],
                                             __nv_bfloat16* sm)
{
    const int tid  = threadIdx.x;
    const int lane = tid & 31;
    const int g    = lane >> 2;
    const int t    = lane & 3;
    const int warp = tid >> 5;
    const int wm   = (warp >> 1) * 32;
    const int wn   = (warp & 1) * 64;
    const int lrow = tid >> 1;            // 0..127
    const int lcol = (tid & 1) * 16;      // 0 / 16
    const int so   = lrow * SSTR + lcol;

    const size_t arow = (size_t)(m0 + lrow) * D_MODEL + lcol;
    const size_t brow = (size_t)(n0 + lrow) * D_MODEL + lcol;

    // prologue: stage 0 <- k-tile 0
    {
        __nv_bfloat16* st = sm;
        cp16(st + so,              Agh + arow); cp16(st + so + 8,              Agh + arow + 8);
        cp16(st + GBUF + so,       Agl + arow); cp16(st + GBUF + so + 8,       Agl + arow + 8);
        cp16(st + 2 * GBUF + so,   Bgh + brow); cp16(st + 2 * GBUF + so + 8,   Bgh + brow + 8);
        cp16(st + 3 * GBUF + so,   Bgl + brow); cp16(st + 3 * GBUF + so + 8,   Bgl + brow + 8);
        CP_COMMIT();
        CP_WAIT0();
    }
    __syncthreads();

    for (int kt = 0; kt < 32; kt++) {
        if (kt + 1 < 32) {
            __nv_bfloat16* nx = sm + ((kt + 1) & 1) * GSTG;
            const int k0 = (kt + 1) * 32;
            cp16(nx + so,            Agh + arow + k0); cp16(nx + so + 8,            Agh + arow + k0 + 8);
            cp16(nx + GBUF + so,     Agl + arow + k0); cp16(nx + GBUF + so + 8,     Agl + arow + k0 + 8);
            cp16(nx + 2 * GBUF + so, Bgh + brow + k0); cp16(nx + 2 * GBUF + so + 8, Bgh + brow + k0 + 8);
            cp16(nx + 3 * GBUF + so, Bgl + brow + k0); cp16(nx + 3 * GBUF + so + 8, Bgl + brow + k0 + 8);
            CP_COMMIT();
        }

        const __nv_bfloat16* Ah = sm + (kt & 1) * GSTG;
        const __nv_bfloat16* Al = Ah + GBUF;
        const __nv_bfloat16* Bh = Ah + 2 * GBUF;
        const __nv_bfloat16* Bl = Ah + 3 * GBUF;

        #pragma unroll
        for (int ks = 0; ks < 2; ks++) {
            const int kk = ks * 16;
            unsigned ahi[2][4], alo[2][4];
            #pragma unroll
            for (int i = 0; i < 2; i++) {
                const int base = (wm + 16 * i + g) * SSTR + kk + 2 * t;
                ahi[i][0] = ld2u(&Ah[base]);
                ahi[i][1] = ld2u(&Ah[base + 8 * SSTR]);
                ahi[i][2] = ld2u(&Ah[base + 8]);
                ahi[i][3] = ld2u(&Ah[base + 8 * SSTR + 8]);
                alo[i][0] = ld2u(&Al[base]);
                alo[i][1] = ld2u(&Al[base + 8 * SSTR]);
                alo[i][2] = ld2u(&Al[base + 8]);
                alo[i][3] = ld2u(&Al[base + 8 * SSTR + 8]);
            }
            #pragma unroll
            for (int j = 0; j < 8; j++) {
                const int bb = (wn + 8 * j + g) * SSTR + kk + 2 * t;
                const unsigned bh0 = ld2u(&Bh[bb]);
                const unsigned bh1 = ld2u(&Bh[bb + 8]);
                const unsigned bl0 = ld2u(&Bl[bb]);
                const unsigned bl1 = ld2u(&Bl[bb + 8]);
                mma16(c[0][j], ahi[0], bh0, bh1);
                mma16(c[1][j], ahi[1], bh0, bh1);
                mma16(c[0][j], alo[0], bh0, bh1);
                mma16(c[1][j], alo[1], bh0, bh1);
                mma16(c[0][j], ahi[0], bl0, bl1);
                mma16(c[1][j], ahi[1], bl0, bl1);
            }
        }
        CP_WAIT0();
        __syncthreads();
    }
}

// Fused QKV projection; blockIdx.z selects weight.
// Q,K -> split bf16 [b,h,s,d]; V -> split bf16 transposed [b,h,d,s].
__global__ __launch_bounds__(256, 2) void gemm_qkv()
{
    extern __shared__ __nv_bfloat16 smg[];
    float c[2][8][4];
    #pragma unroll
    for (int i = 0; i < 2; i++)
        #pragma unroll
        for (int j = 0; j < 8; j++)
            #pragma unroll
            for (int q = 0; q < 4; q++) c[i][j][q] = 0.f;

    const int m0 = blockIdx.y * 128;
    const int n0 = blockIdx.x * 128;
    const int z  = blockIdx.z;

    gemm_bf_body(g_xh, g_xl, g_wh[z], g_wl[z], m0, n0, c, smg);

    const int lane = threadIdx.x & 31;
    const int g = lane >> 2, t = lane & 3;
    const int warp = threadIdx.x >> 5;
    const int wm = (warp >> 1) * 32, wn = (warp & 1) * 64;

    #pragma unroll
    for (int i = 0; i < 2; i++) {
        #pragma unroll
        for (int j = 0; j < 8; j++) {
            const int n = n0 + wn + 8 * j + 2 * t;
            const int h = n >> 6, d = n & 63;
            const int r0 = m0 + wm + 16 * i + g;
            const int r1 = r0 + 8;
            const int b0 = r0 >> 11, s0 = r0 & 2047;
            const int b1 = r1 >> 11, s1 = r1 & 2047;
            __nv_bfloat16 h0, l0, h1, l1, h2, l2, h3, l3;
            split_bf(c[i][j][0], h0, l0); split_bf(c[i][j][1], h1, l1);
            split_bf(c[i][j][2], h2, l2); split_bf(c[i][j][3], h3, l3);
            if (z == 2) {
                // transposed: [b,h,d,s]
                const size_t v0 = ((size_t)(b0 * NUM_HEADS + h) * D_HEAD + d) * SEQ + s0;
                const size_t v1 = ((size_t)(b1 * NUM_HEADS + h) * D_HEAD + d) * SEQ + s1;
                g_vth[v0] = h0; g_vtl[v0] = l0;
                g_vth[v0 + SEQ] = h1; g_vtl[v0 + SEQ] = l1;   // d+1
                g_vth[v1] = h2; g_vtl[v1] = l2;
                g_vth[v1 + SEQ] = h3; g_vtl[v1 + SEQ] = l3;
            } else {
                __nv_bfloat16* dh = (z == 0) ? g_qh : g_kh;
                __nv_bfloat16* dl = (z == 0) ? g_ql : g_kl;
                const size_t i0 = ((size_t)(b0 * NUM_HEADS + h) * SEQ + s0) * D_HEAD + d;
                const size_t i1 = ((size_t)(b1 * NUM_HEADS + h) * SEQ + s1) * D_HEAD + d;
                *(unsigned*)&dh[i0] = pk(h0, h1);
                *(unsigned*)&dl[i0] = pk(l0, l1);
                *(unsigned*)&dh[i1] = pk(h2, h3);
                *(unsigned*)&dl[i1] = pk(l2, l3);
            }
        }
    }
}

// Output projection: out = ctx @ Ow^T, fp32 out.
__global__ __launch_bounds__(256, 2) void gemm_out(float* __restrict__ out)
{
    extern __shared__ __nv_bfloat16 smg[];
    float c[2][8][4];
    #pragma unroll
    for (int i = 0; i < 2; i++)
        #pragma unroll
        for (int j = 0; j < 8; j++)
            #pragma unroll
            for (int q = 0; q < 4; q++) c[i][j][q] = 0.f;

    const int m0 = blockIdx.y * 128;
    const int n0 = blockIdx.x * 128;

    gemm_bf_body(g_ch, g_cl, g_wh[3], g_wl[3], m0, n0, c, smg);

    const int lane = threadIdx.x & 31;
    const int g = lane >> 2, t = lane & 3;
    const int warp = threadIdx.x >> 5;
    const int wm = (warp >> 1) * 32, wn = (warp & 1) * 64;

    #pragma unroll
    for (int i = 0; i < 2; i++) {
        #pragma unroll
        for (int j = 0; j < 8; j++) {
            const int n  = n0 + wn + 8 * j + 2 * t;
            const int r0 = m0 + wm + 16 * i + g;
            *(float2*)&out[(size_t)r0 * D_MODEL + n] = make_float2(c[i][j][0], c[i][j][1]);
            *(float2*)&out[(size_t)(r0 + 8) * D_MODEL + n] = make_float2(c[i][j][2], c[i][j][3]);
        }
    }
}

// ---------------- Flash attention: bf16 tiles via cp.async -------------------
// Block = (b, h, 128-q-tile). 256 threads = 8 warps; warp w owns q rows
// [16w, 16w+16). KV tiles of 64. All operands pre-split bf16 in global.
#define QSTR 72   // bf16 stride (64+8): conflict-free frag loads

// element offsets (bf16 units)
#define OFF_QH 0
#define OFF_QL (128 * QSTR)
#define OFF_KH (2 * 128 * QSTR)
#define OFF_KL (OFF_KH + 64 * QSTR)
#define OFF_VH (OFF_KL + 64 * QSTR)
#define OFF_VL (OFF_VH + 64 * QSTR)
#define OFF_PH (OFF_VL + 64 * QSTR)
#define OFF_PL (OFF_PH + 128 * QSTR)
#define ATTN_SMEM ((OFF_PL + 128 * QSTR) * 2)   // 110592 bytes

__global__ __launch_bounds__(256, 2) void attn_mma(const unsigned char* __restrict__ pm)
{
    extern __shared__ __nv_bfloat16 smb[];
    __nv_bfloat16* Qh  = smb + OFF_QH;
    __nv_bfloat16* Ql  = smb + OFF_QL;
    __nv_bfloat16* Kh  = smb + OFF_KH;
    __nv_bfloat16* Kl  = smb + OFF_KL;
    __nv_bfloat16* Vth = smb + OFF_VH;   // [dv][c]
    __nv_bfloat16* Vtl = smb + OFF_VL;
    __nv_bfloat16* Ph  = smb + OFF_PH;
    __nv_bfloat16* Pl  = smb + OFF_PL;

    const int qt = gridDim.x - 1 - blockIdx.x;   // heavy blocks first
    const int h  = blockIdx.y;
    const int b  = blockIdx.z;
    const int tid  = threadIdx.x;
    const int lane = tid & 31;
    const int warp = tid >> 5;
    const int g = lane >> 2, t = lane & 3;
    const size_t base = (size_t)(b * NUM_HEADS + h) * SEQ;

    // ---- Q tile [128][64] (both halves) via cp.async ----
    {
        const int row = tid >> 1;              // 0..127
        const int cs  = (tid & 1) * 32;        // 0 / 32
        const size_t ga = (base + (size_t)qt * 128 + row) * D_HEAD + cs;
        const int so = row * QSTR + cs;
        #pragma unroll
        for (int u = 0; u < 4; u++) {
            cp16(&Qh[so + 8 * u], &g_qh[ga + 8 * u]);
            cp16(&Ql[so + 8 * u], &g_ql[ga + 8 * u]);
        }
        CP_COMMIT();
    }

    float o[8][4];
    float m_i[2] = {-1e30f, -1e30f};
    float l_i[2] = {0.f, 0.f};
    #pragma unroll
    for (int j = 0; j < 8; j++)
        #pragma unroll
        for (int q = 0; q < 4; q++) o[j][q] = 0.f;

    const int rw = warp * 16;
    const int Rg = qt * 128 + rw;
    const int kt_max = 2 * qt + 1;

    const int krow = tid >> 2;                  // 0..63
    const int kcs  = (tid & 3) * 16;            // 0/16/32/48
    const int kso  = krow * QSTR + kcs;

    for (int kt = 0; kt <= kt_max; kt++) {
        __syncthreads();   // prior readers of K/V/P done

        // ---- K tile [64][64] + Vt tile [64][64] via cp.async ----
        {
            const size_t gk = (base + (size_t)kt * 64 + krow) * D_HEAD + kcs;
            cp16(&Kh[kso],     &g_kh[gk]);
            cp16(&Kh[kso + 8], &g_kh[gk + 8]);
            cp16(&Kl[kso],     &g_kl[gk]);
            cp16(&Kl[kso + 8], &g_kl[gk + 8]);
            // Vt: global [b,h,d,s]; row = d, cols = s segment
            const size_t gv = ((size_t)(b * NUM_HEADS + h) * D_HEAD + krow) * SEQ
                              + (size_t)kt * 64 + kcs;
            cp16(&Vth[kso],     &g_vth[gv]);
            cp16(&Vth[kso + 8], &g_vth[gv + 8]);
            cp16(&Vtl[kso],     &g_vtl[gv]);
            cp16(&Vtl[kso + 8], &g_vtl[gv + 8]);
            CP_COMMIT();
            CP_WAIT0();
        }
        __syncthreads();

        const int C0 = kt * 64;
        if (C0 > Rg + 15) continue;              // strip fully masked (causal)

        // ---- S = Q @ K^T (split-bf16, 4 k-steps of 16) ----
        float s[8][4];
        #pragma unroll
        for (int j = 0; j < 8; j++)
            #pragma unroll
            for (int q = 0; q < 4; q++) s[j][q] = 0.f;

        #pragma unroll
        for (int ks = 0; ks < 4; ks++) {
            const int kk = ks * 16;
            const int ab = (rw + g) * QSTR + kk + 2 * t;
            unsigned ahi[4], alo[4];
            ahi[0] = ld2u(&Qh[ab]);
            ahi[1] = ld2u(&Qh[ab + 8 * QSTR]);
            ahi[2] = ld2u(&Qh[ab + 8]);
            ahi[3] = ld2u(&Qh[ab + 8 * QSTR + 8]);
            alo[0] = ld2u(&Ql[ab]);
            alo[1] = ld2u(&Ql[ab + 8 * QSTR]);
            alo[2] = ld2u(&Ql[ab + 8]);
            alo[3] = ld2u(&Ql[ab + 8 * QSTR + 8]);
            #pragma unroll
            for (int j = 0; j < 8; j++) {
                const int bb = (8 * j + g) * QSTR + kk + 2 * t;
                const unsigned bh0 = ld2u(&Kh[bb]);
                const unsigned bh1 = ld2u(&Kh[bb + 8]);
                const unsigned bl0 = ld2u(&Kl[bb]);
                const unsigned bl1 = ld2u(&Kl[bb + 8]);
                mma16(s[j], ahi, bh0, bh1);
                mma16(s[j], alo, bh0, bh1);
                mma16(s[j], ahi, bl0, bl1);
            }
        }

        // ---- scale (log2 domain) + causal + padding masks ----
        const unsigned char* pmb = pm + (size_t)b * SEQ + C0;
        const int r0 = Rg + g, r1 = r0 + 8;
        #pragma unroll
        for (int j = 0; j < 8; j++) {
            const int c0 = C0 + 8 * j + 2 * t, c1 = c0 + 1;
            const bool p0 = pmb[8 * j + 2 * t] != 0;
            const bool p1 = pmb[8 * j + 2 * t + 1] != 0;
            float v;
            v = s[j][0] * SCALE_LOG2E; if (c0 > r0 || p0) v = -1e30f; s[j][0] = v;
            v = s[j][1] * SCALE_LOG2E; if (c1 > r0 || p1) v = -1e30f; s[j][1] = v;
            v = s[j][2] * SCALE_LOG2E; if (c0 > r1 || p0) v = -1e30f; s[j][2] = v;
            v = s[j][3] * SCALE_LOG2E; if (c1 > r1 || p1) v = -1e30f; s[j][3] = v;
        }

        // ---- online softmax, base-2, FMA-pipe exp ----
        #pragma unroll
        for (int rr = 0; rr < 2; rr++) {
            float rm = -1e30f;
            #pragma unroll
            for (int j = 0; j < 8; j++)
                rm = fmaxf(rm, fmaxf(s[j][2 * rr], s[j][2 * rr + 1]));
            rm = fmaxf(rm, __shfl_xor_sync(0xffffffffu, rm, 1));
            rm = fmaxf(rm, __shfl_xor_sync(0xffffffffu, rm, 2));
            const float mn    = fmaxf(m_i[rr], rm);
            const float alpha = exp2_fast(m_i[rr] - mn);
            m_i[rr] = mn;
            float rs = 0.f;
            #pragma unroll
            for (int j = 0; j < 8; j++) {
                s[j][2 * rr    ] = exp2_fast(s[j][2 * rr    ] - mn);
                s[j][2 * rr + 1] = exp2_fast(s[j][2 * rr + 1] - mn);
                rs += s[j][2 * rr] + s[j][2 * rr + 1];
            }
            rs += __shfl_xor_sync(0xffffffffu, rs, 1);
            rs += __shfl_xor_sync(0xffffffffu, rs, 2);
            l_i[rr] = l_i[rr] * alpha + rs;
            #pragma unroll
            for (int j = 0; j < 8; j++) {
                o[j][2 * rr    ] *= alpha;
                o[j][2 * rr + 1] *= alpha;
            }
        }

        // ---- split-write P (warp-private rows; __syncwarp suffices) ----
        #pragma unroll
        for (int j = 0; j < 8; j++) {
            __nv_bfloat16 h0, l0, h1, l1, h2, l2, h3, l3;
            split_bf(s[j][0], h0, l0); split_bf(s[j][1], h1, l1);
            split_bf(s[j][2], h2, l2); split_bf(s[j][3], h3, l3);
            const int p0 = (rw + g) * QSTR + 8 * j + 2 * t;
            const int p1 = p0 + 8 * QSTR;
            *(unsigned*)&Ph[p0] = pk(h0, h1);
            *(unsigned*)&Pl[p0] = pk(l0, l1);
            *(unsigned*)&Ph[p1] = pk(h2, h3);
            *(unsigned*)&Pl[p1] = pk(l2, l3);
        }
        __syncwarp();

        // ---- O += P @ V (split-bf16, 4 k-steps over c) ----
        #pragma unroll
        for (int ks = 0; ks < 4; ks++) {
            const int kk = ks * 16;
            const int ab = (rw + g) * QSTR + kk + 2 * t;
            unsigned ahi[4], alo[4];
            ahi[0] = ld2u(&Ph[ab]);
            ahi[1] = ld2u(&Ph[ab + 8 * QSTR]);
            ahi[2] = ld2u(&Ph[ab + 8]);
            ahi[3] = ld2u(&Ph[ab + 8 * QSTR + 8]);
            alo[0] = ld2u(&Pl[ab]);
            alo[1] = ld2u(&Pl[ab + 8 * QSTR]);
            alo[2] = ld2u(&Pl[ab + 8]);
            alo[3] = ld2u(&Pl[ab + 8 * QSTR + 8]);
            #pragma unroll
            for (int j = 0; j < 8; j++) {
                const int bb = (8 * j + g) * QSTR + kk + 2 * t;
                const unsigned bh0 = ld2u(&Vth[bb]);
                const unsigned bh1 = ld2u(&Vth[bb + 8]);
                const unsigned bl0 = ld2u(&Vtl[bb]);
                const unsigned bl1 = ld2u(&Vtl[bb + 8]);
                mma16(o[j], ahi, bh0, bh1);
                mma16(o[j], alo, bh0, bh1);
                mma16(o[j], ahi, bl0, bl1);
            }
        }
    }

    // ---- normalize + split-write ctx [b, s, h*64 + col] ----
    const float inv0 = 1.f / l_i[0];
    const float inv1 = 1.f / l_i[1];
    const int row0 = qt * 128 + rw + g;
    const size_t d0 = ((size_t)b * SEQ + row0    ) * D_MODEL + h * D_HEAD;
    const size_t d1 = ((size_t)b * SEQ + row0 + 8) * D_MODEL + h * D_HEAD;
    #pragma unroll
    for (int j = 0; j < 8; j++) {
        const int cidx = 8 * j + 2 * t;
        __nv_bfloat16 h0, l0, h1, l1, h2, l2, h3, l3;
        split_bf(o[j][0] * inv0, h0, l0); split_bf(o[j][1] * inv0, h1, l1);
        split_bf(o[j][2] * inv1, h2, l2); split_bf(o[j][3] * inv1, h3, l3);
        *(unsigned*)&g_ch[d0 + cidx] = pk(h0, h1);
        *(unsigned*)&g_cl[d0 + cidx] = pk(l0, l1);
        *(unsigned*)&g_ch[d1 + cidx] = pk(h2, h3);
        *(unsigned*)&g_cl[d1 + cidx] = pk(l2, l3);
    }
}

// ---------------- launch ----------------------------------------------------
extern "C" void kernel_launch(void* const* d_in, const int* in_sizes, int n_in,
                              void* d_out, int out_size)
{
    (void)in_sizes; (void)n_in; (void)out_size;
    const float* x  = (const float*)d_in[0];
    const float* Qw = (const float*)d_in[1];
    const float* Kw = (const float*)d_in[2];
    const float* Vw = (const float*)d_in[3];
    const float* Ow = (const float*)d_in[4];
    const unsigned char* pm = (const unsigned char*)d_in[5];
    float* out = (float*)d_out;

    cudaFuncSetAttribute(attn_mma, cudaFuncAttributeMaxDynamicSharedMemorySize, ATTN_SMEM);
    cudaFuncSetAttribute(gemm_qkv, cudaFuncAttributeMaxDynamicSharedMemorySize, GEMM_SMEM);
    cudaFuncSetAttribute(gemm_out, cudaFuncAttributeMaxDynamicSharedMemorySize, GEMM_SMEM);

    split_all<<<12288, 256>>>(x, Qw, Kw, Vw, Ow);

    dim3 gq(D_MODEL / 128, MTOT / 128, 3);        // 8 x 64 x 3
    gemm_qkv<<<gq, 256, GEMM_SMEM>>>();

    dim3 ga(SEQ / 128, NUM_HEADS, BATCH);         // 16 x 16 x 4
    attn_mma<<<ga, 256, ATTN_SMEM>>>(pm);

    dim3 go(D_MODEL / 128, MTOT / 128);           // 8 x 64
    gemm_out<<<go, 256, GEMM_SMEM>>>(out);
}

// round 6
// speedup vs baseline: 3.9075x; 1.0394x over previous
#include <cuda_runtime.h>
#include <cuda_bf16.h>
#include <cstdint>

#define D_MODEL   1024
#define NUM_HEADS 16
#define D_HEAD    64
#define BATCH     4
#define SEQ       2048
#define MTOT      (BATCH * SEQ)   // 8192
#define QKV_EL    (BATCH * NUM_HEADS * SEQ * D_HEAD)   // 8388608

// ---------------- scratch (device globals: allocation-guard safe) ----------
__device__ __nv_bfloat16 g_xh[MTOT * D_MODEL],  g_xl[MTOT * D_MODEL];
__device__ __nv_bfloat16 g_wh[4][D_MODEL * D_MODEL], g_wl[4][D_MODEL * D_MODEL];
__device__ __nv_bfloat16 g_qh[QKV_EL], g_ql[QKV_EL];          // [b,h,s,d]
__device__ __nv_bfloat16 g_kh[QKV_EL], g_kl[QKV_EL];          // [b,h,s,d]
__device__ __nv_bfloat16 g_vth[QKV_EL], g_vtl[QKV_EL];        // [b,h,d,s]
__device__ __nv_bfloat16 g_ch[MTOT * D_MODEL], g_cl[MTOT * D_MODEL];   // ctx

// ---------------- helpers ----------------------------------------------------
__device__ __forceinline__ void split_bf(float x, __nv_bfloat16& h, __nv_bfloat16& l) {
    h = __float2bfloat16(x);
    l = __float2bfloat16(x - __bfloat162float(h));
}
__device__ __forceinline__ unsigned pk(__nv_bfloat16 a, __nv_bfloat16 b) {
    return (unsigned)__bfloat16_as_ushort(a) | ((unsigned)__bfloat16_as_ushort(b) << 16);
}
__device__ __forceinline__ void split_store4(float4 v, __nv_bfloat16* hp, __nv_bfloat16* lp) {
    __nv_bfloat16 h0, l0, h1, l1, h2, l2, h3, l3;
    split_bf(v.x, h0, l0); split_bf(v.y, h1, l1);
    split_bf(v.z, h2, l2); split_bf(v.w, h3, l3);
    *(uint2*)hp = make_uint2(pk(h0, h1), pk(h2, h3));
    *(uint2*)lp = make_uint2(pk(l0, l1), pk(l2, l3));
}
__device__ __forceinline__ void mma16(float* c, const unsigned* a, unsigned b0, unsigned b1) {
    asm volatile(
        "mma.sync.aligned.m16n8k16.row.col.f32.bf16.bf16.f32 "
        "{%0,%1,%2,%3}, {%4,%5,%6,%7}, {%8,%9}, {%0,%1,%2,%3};"
        : "+f"(c[0]), "+f"(c[1]), "+f"(c[2]), "+f"(c[3])
        : "r"(a[0]), "r"(a[1]), "r"(a[2]), "r"(a[3]), "r"(b0), "r"(b1));
}
__device__ __forceinline__ void ldsm4(unsigned r[4], const __nv_bfloat16* p) {
    unsigned a = (unsigned)__cvta_generic_to_shared(p);
    asm volatile("ldmatrix.sync.aligned.m8n8.x4.shared.b16 {%0,%1,%2,%3}, [%4];"
                 : "=r"(r[0]), "=r"(r[1]), "=r"(r[2]), "=r"(r[3]) : "r"(a));
}
__device__ __forceinline__ void cp16(__nv_bfloat16* s, const __nv_bfloat16* g) {
    unsigned sa = (unsigned)__cvta_generic_to_shared(s);
    asm volatile("cp.async.cg.shared.global [%0], [%1], 16;" :: "r"(sa), "l"(g));
}
#define CP_COMMIT() asm volatile("cp.async.commit_group;")
#define CP_WAIT0()  asm volatile("cp.async.wait_group 0;")
#define CP_WAIT1()  asm volatile("cp.async.wait_group 1;")

// fast exp2 on the FMA pipe (MUFU-free)
__device__ __forceinline__ float exp2_fast(float y) {
    y = fmaxf(y, -120.f);
    float z = y + 12582912.f;
    int   e = __float_as_int(z);
    float f = y - (z - 12582912.f);
    float p = 1.f + f * (0.6931471805599453f + f * (0.2402265069591007f +
              f * (0.0555041086648216f + f * (0.0096181291076285f +
              f * 0.0013333558146429f))));
    return __int_as_float(__float_as_int(p) + (e << 23));
}
#define SCALE_LOG2E 0.18033688011112042f   // 0.125 * log2(e)

// ---------------- one-shot split of x + weights ------------------------------
__global__ __launch_bounds__(256) void split_all(const float* __restrict__ x,
                                                 const float* __restrict__ Qw,
                                                 const float* __restrict__ Kw,
                                                 const float* __restrict__ Vw,
                                                 const float* __restrict__ Ow)
{
    const int idx = blockIdx.x * 256 + threadIdx.x;        // one float4 each
    const float* src;
    __nv_bfloat16 *hp, *lp;
    size_t off;
    if (idx < 2097152) {
        src = x; off = idx; hp = g_xh; lp = g_xl;
    } else {
        const int w = (idx - 2097152) >> 18;
        off = (size_t)((idx - 2097152) & 262143);
        src = (w == 0) ? Qw : (w == 1) ? Kw : (w == 2) ? Vw : Ow;
        hp = g_wh[w]; lp = g_wl[w];
    }
    float4 v = ((const float4*)src)[off];
    split_store4(v, hp + off * 4, lp + off * 4);
}

// ---------------- split-bf16 GEMM, cp.async + ldmatrix -----------------------
// Block tile 128x128, BK=32, 256 threads = 8 warps (4m x 2n), warp tile 32x64.
#define SSTR 40                       // bf16 stride: LDSM phases conflict-free
#define GBUF (128 * SSTR)
#define GSTG (4 * GBUF)
#define GEMM_SMEM (2 * GSTG * 2)      // 81920 bytes

__device__ __forceinline__ void gemm_bf_body(const __nv_bfloat16* __restrict__ Agh,
                                             const __nv_bfloat16* __restrict__ Agl,
                                             const __nv_bfloat16* __restrict__ Bgh,
                                             const __nv_bfloat16* __restrict__ Bgl,
                                             int m0, int n0,
                                             float (&c)[2][8][4],
                                             __nv_bfloat16* sm)
{
    const int tid  = threadIdx.x;
    const int lane = tid & 31;
    const int warp = tid >> 5;
    const int wm   = (warp >> 1) * 32;
    const int wn   = (warp & 1) * 64;
    const int lrow = tid >> 1;
    const int lcol = (tid & 1) * 16;
    const int so   = lrow * SSTR + lcol;

    // ldmatrix per-lane offsets
    const int aoff = ((lane & 7) + ((lane >> 3) & 1) * 8) * SSTR + (lane >> 4) * 8;
    const int boff = ((lane & 7) + (lane >> 4) * 8) * SSTR + ((lane >> 3) & 1) * 8;

    const size_t arow = (size_t)(m0 + lrow) * D_MODEL + lcol;
    const size_t brow = (size_t)(n0 + lrow) * D_MODEL + lcol;

    {   // prologue: stage 0 <- k-tile 0
        __nv_bfloat16* st = sm;
        cp16(st + so,            Agh + arow); cp16(st + so + 8,            Agh + arow + 8);
        cp16(st + GBUF + so,     Agl + arow); cp16(st + GBUF + so + 8,     Agl + arow + 8);
        cp16(st + 2 * GBUF + so, Bgh + brow); cp16(st + 2 * GBUF + so + 8, Bgh + brow + 8);
        cp16(st + 3 * GBUF + so, Bgl + brow); cp16(st + 3 * GBUF + so + 8, Bgl + brow + 8);
        CP_COMMIT();
        CP_WAIT0();
    }
    __syncthreads();

    for (int kt = 0; kt < 32; kt++) {
        if (kt + 1 < 32) {
            __nv_bfloat16* nx = sm + ((kt + 1) & 1) * GSTG;
            const int k0 = (kt + 1) * 32;
            cp16(nx + so,            Agh + arow + k0); cp16(nx + so + 8,            Agh + arow + k0 + 8);
            cp16(nx + GBUF + so,     Agl + arow + k0); cp16(nx + GBUF + so + 8,     Agl + arow + k0 + 8);
            cp16(nx + 2 * GBUF + so, Bgh + brow + k0); cp16(nx + 2 * GBUF + so + 8, Bgh + brow + k0 + 8);
            cp16(nx + 3 * GBUF + so, Bgl + brow + k0); cp16(nx + 3 * GBUF + so + 8, Bgl + brow + k0 + 8);
            CP_COMMIT();
        }

        const __nv_bfloat16* Ah = sm + (kt & 1) * GSTG;
        const __nv_bfloat16* Al = Ah + GBUF;
        const __nv_bfloat16* Bh = Ah + 2 * GBUF;
        const __nv_bfloat16* Bl = Ah + 3 * GBUF;

        #pragma unroll
        for (int ks = 0; ks < 2; ks++) {
            const int kk = ks * 16;
            unsigned ahi[2][4], alo[2][4];
            ldsm4(ahi[0], Ah + (wm     ) * SSTR + kk + aoff);
            ldsm4(ahi[1], Ah + (wm + 16) * SSTR + kk + aoff);
            ldsm4(alo[0], Al + (wm     ) * SSTR + kk + aoff);
            ldsm4(alo[1], Al + (wm + 16) * SSTR + kk + aoff);
            #pragma unroll
            for (int jp = 0; jp < 4; jp++) {
                unsigned bh[4], bl[4];
                ldsm4(bh, Bh + (wn + 16 * jp) * SSTR + kk + boff);
                ldsm4(bl, Bl + (wn + 16 * jp) * SSTR + kk + boff);
                const int j0 = 2 * jp, j1 = 2 * jp + 1;
                mma16(c[0][j0], ahi[0], bh[0], bh[1]);
                mma16(c[1][j0], ahi[1], bh[0], bh[1]);
                mma16(c[0][j0], alo[0], bh[0], bh[1]);
                mma16(c[1][j0], alo[1], bh[0], bh[1]);
                mma16(c[0][j0], ahi[0], bl[0], bl[1]);
                mma16(c[1][j0], ahi[1], bl[0], bl[1]);
                mma16(c[0][j1], ahi[0], bh[2], bh[3]);
                mma16(c[1][j1], ahi[1], bh[2], bh[3]);
                mma16(c[0][j1], alo[0], bh[2], bh[3]);
                mma16(c[1][j1], alo[1], bh[2], bh[3]);
                mma16(c[0][j1], ahi[0], bl[2], bl[3]);
                mma16(c[1][j1], ahi[1], bl[2], bl[3]);
            }
        }
        CP_WAIT0();
        __syncthreads();
    }
}

// Fused QKV projection; blockIdx.z selects weight.
__global__ __launch_bounds__(256, 2) void gemm_qkv()
{
    extern __shared__ __nv_bfloat16 smg[];
    float c[2][8][4];
    #pragma unroll
    for (int i = 0; i < 2; i++)
        #pragma unroll
        for (int j = 0; j < 8; j++)
            #pragma unroll
            for (int q = 0; q < 4; q++) c[i][j][q] = 0.f;

    const int m0 = blockIdx.y * 128;
    const int n0 = blockIdx.x * 128;
    const int z  = blockIdx.z;

    gemm_bf_body(g_xh, g_xl, g_wh[z], g_wl[z], m0, n0, c, smg);

    const int lane = threadIdx.x & 31;
    const int g = lane >> 2, t = lane & 3;
    const int warp = threadIdx.x >> 5;
    const int wm = (warp >> 1) * 32, wn = (warp & 1) * 64;

    #pragma unroll
    for (int i = 0; i < 2; i++) {
        #pragma unroll
        for (int j = 0; j < 8; j++) {
            const int n = n0 + wn + 8 * j + 2 * t;
            const int h = n >> 6, d = n & 63;
            const int r0 = m0 + wm + 16 * i + g;
            const int r1 = r0 + 8;
            const int b0 = r0 >> 11, s0 = r0 & 2047;
            const int b1 = r1 >> 11, s1 = r1 & 2047;
            __nv_bfloat16 h0, l0, h1, l1, h2, l2, h3, l3;
            split_bf(c[i][j][0], h0, l0); split_bf(c[i][j][1], h1, l1);
            split_bf(c[i][j][2], h2, l2); split_bf(c[i][j][3], h3, l3);
            if (z == 2) {
                const size_t v0 = ((size_t)(b0 * NUM_HEADS + h) * D_HEAD + d) * SEQ + s0;
                const size_t v1 = ((size_t)(b1 * NUM_HEADS + h) * D_HEAD + d) * SEQ + s1;
                g_vth[v0] = h0; g_vtl[v0] = l0;
                g_vth[v0 + SEQ] = h1; g_vtl[v0 + SEQ] = l1;
                g_vth[v1] = h2; g_vtl[v1] = l2;
                g_vth[v1 + SEQ] = h3; g_vtl[v1 + SEQ] = l3;
            } else {
                __nv_bfloat16* dh = (z == 0) ? g_qh : g_kh;
                __nv_bfloat16* dl = (z == 0) ? g_ql : g_kl;
                const size_t i0 = ((size_t)(b0 * NUM_HEADS + h) * SEQ + s0) * D_HEAD + d;
                const size_t i1 = ((size_t)(b1 * NUM_HEADS + h) * SEQ + s1) * D_HEAD + d;
                *(unsigned*)&dh[i0] = pk(h0, h1);
                *(unsigned*)&dl[i0] = pk(l0, l1);
                *(unsigned*)&dh[i1] = pk(h2, h3);
                *(unsigned*)&dl[i1] = pk(l2, l3);
            }
        }
    }
}

// Output projection: out = ctx @ Ow^T, fp32 out.
__global__ __launch_bounds__(256, 2) void gemm_out(float* __restrict__ out)
{
    extern __shared__ __nv_bfloat16 smg[];
    float c[2][8][4];
    #pragma unroll
    for (int i = 0; i < 2; i++)
        #pragma unroll
        for (int j = 0; j < 8; j++)
            #pragma unroll
            for (int q = 0; q < 4; q++) c[i][j][q] = 0.f;

    const int m0 = blockIdx.y * 128;
    const int n0 = blockIdx.x * 128;

    gemm_bf_body(g_ch, g_cl, g_wh[3], g_wl[3], m0, n0, c, smg);

    const int lane = threadIdx.x & 31;
    const int g = lane >> 2, t = lane & 3;
    const int warp = threadIdx.x >> 5;
    const int wm = (warp >> 1) * 32, wn = (warp & 1) * 64;

    #pragma unroll
    for (int i = 0; i < 2; i++) {
        #pragma unroll
        for (int j = 0; j < 8; j++) {
            const int n  = n0 + wn + 8 * j + 2 * t;
            const int r0 = m0 + wm + 16 * i + g;
            *(float2*)&out[(size_t)r0 * D_MODEL + n] = make_float2(c[i][j][0], c[i][j][1]);
            *(float2*)&out[(size_t)(r0 + 8) * D_MODEL + n] = make_float2(c[i][j][2], c[i][j][3]);
        }
    }
}

// ---------------- Flash attention: Q-in-regs, KV double-buffer, ldmatrix -----
// Block = (b, h, 128-q-tile). 256 threads = 8 warps; warp w owns q rows
// [16w, 16w+16). KV tiles of 64.
#define QSTR 72
#define TILEC (64 * QSTR)                 // 4608 elems = one 64x64 half-tile
#define ATTN_SMEM (12 * TILEC * 2)        // 110592 bytes

__global__ __launch_bounds__(256, 2) void attn_mma(const unsigned char* __restrict__ pm)
{
    extern __shared__ __nv_bfloat16 smb[];
    __nv_bfloat16* stg0 = smb;                  // KV stage 0: Kh,Kl,Vh,Vl
    __nv_bfloat16* stg1 = smb + 4 * TILEC;      // KV stage 1 (Q staging first)
    __nv_bfloat16* Ph   = smb + 8 * TILEC;
    __nv_bfloat16* Pl   = smb + 10 * TILEC;

    const int qt = gridDim.x - 1 - blockIdx.x;
    const int h  = blockIdx.y;
    const int b  = blockIdx.z;
    const int tid  = threadIdx.x;
    const int lane = tid & 31;
    const int warp = tid >> 5;
    const int g = lane >> 2, t = lane & 3;
    const size_t base = (size_t)(b * NUM_HEADS + h) * SEQ;

    const int rw = warp * 16;
    const int Rg = qt * 128 + rw;
    const int kt_max = 2 * qt + 1;

    // ldmatrix per-lane offsets (QSTR-strided)
    const int aoffQ = ((lane & 7) + ((lane >> 3) & 1) * 8) * QSTR + (lane >> 4) * 8;
    const int boffQ = ((lane & 7) + (lane >> 4) * 8) * QSTR + ((lane >> 3) & 1) * 8;

    // KV loader indices
    const int krow = tid >> 2;                // 0..63
    const int kcs  = (tid & 3) * 16;          // 0/16/32/48
    const int kso  = krow * QSTR + kcs;
    const size_t vbase = ((size_t)(b * NUM_HEADS + h) * D_HEAD + krow) * SEQ + kcs;
    const size_t kbase = (base + krow) * D_HEAD + kcs;

    // ---- stage Q into stg1 + KV(0) into stg0 ----
    {
        const int row = tid >> 1, cs = (tid & 1) * 32;
        const size_t ga = (base + (size_t)qt * 128 + row) * D_HEAD + cs;
        const int so = row * QSTR + cs;
        __nv_bfloat16* Qsh = stg1;
        __nv_bfloat16* Qsl = stg1 + 2 * TILEC;
        #pragma unroll
        for (int u = 0; u < 4; u++) {
            cp16(&Qsh[so + 8 * u], &g_qh[ga + 8 * u]);
            cp16(&Qsl[so + 8 * u], &g_ql[ga + 8 * u]);
        }
        CP_COMMIT();
    }
    {
        cp16(&stg0[kso],             &g_kh[kbase]); cp16(&stg0[kso + 8],             &g_kh[kbase + 8]);
        cp16(&stg0[TILEC + kso],     &g_kl[kbase]); cp16(&stg0[TILEC + kso + 8],     &g_kl[kbase + 8]);
        cp16(&stg0[2 * TILEC + kso], &g_vth[vbase]); cp16(&stg0[2 * TILEC + kso + 8], &g_vth[vbase + 8]);
        cp16(&stg0[3 * TILEC + kso], &g_vtl[vbase]); cp16(&stg0[3 * TILEC + kso + 8], &g_vtl[vbase + 8]);
        CP_COMMIT();
    }
    CP_WAIT1();                       // Q staged (KV0 may still be in flight)
    __syncthreads();

    // ---- Q fragments to registers (once) ----
    unsigned qh[4][4], ql[4][4];
    #pragma unroll
    for (int ks = 0; ks < 4; ks++) {
        ldsm4(qh[ks], stg1 + rw * QSTR + 16 * ks + aoffQ);
        ldsm4(ql[ks], stg1 + 2 * TILEC + rw * QSTR + 16 * ks + aoffQ);
    }
    __syncthreads();                  // stg1 free for KV(1)

    float o[8][4];
    float m_i[2] = {-1e30f, -1e30f};
    float l_i[2] = {0.f, 0.f};
    #pragma unroll
    for (int j = 0; j < 8; j++)
        #pragma unroll
        for (int q = 0; q < 4; q++) o[j][q] = 0.f;

    for (int kt = 0; kt <= kt_max; kt++) {
        // prefetch KV(kt+1) into the other stage
        if (kt < kt_max) {
            __nv_bfloat16* nx = ((kt + 1) & 1) ? stg1 : stg0;
            const size_t gk = kbase + (size_t)(kt + 1) * 64 * D_HEAD;
            const size_t gv = vbase + (size_t)(kt + 1) * 64;
            cp16(&nx[kso],             &g_kh[gk]);  cp16(&nx[kso + 8],             &g_kh[gk + 8]);
            cp16(&nx[TILEC + kso],     &g_kl[gk]);  cp16(&nx[TILEC + kso + 8],     &g_kl[gk + 8]);
            cp16(&nx[2 * TILEC + kso], &g_vth[gv]); cp16(&nx[2 * TILEC + kso + 8], &g_vth[gv + 8]);
            cp16(&nx[3 * TILEC + kso], &g_vtl[gv]); cp16(&nx[3 * TILEC + kso + 8], &g_vtl[gv + 8]);
            CP_COMMIT();
            CP_WAIT1();               // KV(kt) complete
        } else {
            CP_WAIT0();
        }
        __syncthreads();              // KV(kt) visible

        const int C0 = kt * 64;
        if (C0 <= Rg + 15) {          // warp strip not fully masked
            const __nv_bfloat16* Kh = (kt & 1) ? stg1 : stg0;
            const __nv_bfloat16* Kl = Kh + TILEC;
            const __nv_bfloat16* Vh = Kh + 2 * TILEC;
            const __nv_bfloat16* Vl = Kh + 3 * TILEC;

            // ---- S = Q @ K^T ----
            float s[8][4];
            #pragma unroll
            for (int j = 0; j < 8; j++)
                #pragma unroll
                for (int q = 0; q < 4; q++) s[j][q] = 0.f;

            #pragma unroll
            for (int ks = 0; ks < 4; ks++) {
                const int kk = 16 * ks;
                #pragma unroll
                for (int jp = 0; jp < 4; jp++) {
                    unsigned bh[4], bl[4];
                    ldsm4(bh, Kh + (16 * jp) * QSTR + kk + boffQ);
                    ldsm4(bl, Kl + (16 * jp) * QSTR + kk + boffQ);
                    const int j0 = 2 * jp, j1 = j0 + 1;
                    mma16(s[j0], qh[ks], bh[0], bh[1]);
                    mma16(s[j0], ql[ks], bh[0], bh[1]);
                    mma16(s[j0], qh[ks], bl[0], bl[1]);
                    mma16(s[j1], qh[ks], bh[2], bh[3]);
                    mma16(s[j1], ql[ks], bh[2], bh[3]);
                    mma16(s[j1], qh[ks], bl[2], bl[3]);
                }
            }

            // ---- scale (log2 domain) + causal + padding masks ----
            const unsigned char* pmb = pm + (size_t)b * SEQ + C0;
            const int r0 = Rg + g, r1 = r0 + 8;
            #pragma unroll
            for (int j = 0; j < 8; j++) {
                const int c0 = C0 + 8 * j + 2 * t, c1 = c0 + 1;
                const bool p0 = pmb[8 * j + 2 * t] != 0;
                const bool p1 = pmb[8 * j + 2 * t + 1] != 0;
                float v;
                v = s[j][0] * SCALE_LOG2E; if (c0 > r0 || p0) v = -1e30f; s[j][0] = v;
                v = s[j][1] * SCALE_LOG2E; if (c1 > r0 || p1) v = -1e30f; s[j][1] = v;
                v = s[j][2] * SCALE_LOG2E; if (c0 > r1 || p0) v = -1e30f; s[j][2] = v;
                v = s[j][3] * SCALE_LOG2E; if (c1 > r1 || p1) v = -1e30f; s[j][3] = v;
            }

            // ---- online softmax, base-2, FMA-pipe exp ----
            #pragma unroll
            for (int rr = 0; rr < 2; rr++) {
                float rm = -1e30f;
                #pragma unroll
                for (int j = 0; j < 8; j++)
                    rm = fmaxf(rm, fmaxf(s[j][2 * rr], s[j][2 * rr + 1]));
                rm = fmaxf(rm, __shfl_xor_sync(0xffffffffu, rm, 1));
                rm = fmaxf(rm, __shfl_xor_sync(0xffffffffu, rm, 2));
                const float mn    = fmaxf(m_i[rr], rm);
                const float alpha = exp2_fast(m_i[rr] - mn);
                m_i[rr] = mn;
                float rs = 0.f;
                #pragma unroll
                for (int j = 0; j < 8; j++) {
                    s[j][2 * rr    ] = exp2_fast(s[j][2 * rr    ] - mn);
                    s[j][2 * rr + 1] = exp2_fast(s[j][2 * rr + 1] - mn);
                    rs += s[j][2 * rr] + s[j][2 * rr + 1];
                }
                rs += __shfl_xor_sync(0xffffffffu, rs, 1);
                rs += __shfl_xor_sync(0xffffffffu, rs, 2);
                l_i[rr] = l_i[rr] * alpha + rs;
                #pragma unroll
                for (int j = 0; j < 8; j++) {
                    o[j][2 * rr    ] *= alpha;
                    o[j][2 * rr + 1] *= alpha;
                }
            }

            // ---- split-write P (warp-private rows) ----
            #pragma unroll
            for (int j = 0; j < 8; j++) {
                __nv_bfloat16 h0, l0, h1, l1, h2, l2, h3, l3;
                split_bf(s[j][0], h0, l0); split_bf(s[j][1], h1, l1);
                split_bf(s[j][2], h2, l2); split_bf(s[j][3], h3, l3);
                const int p0 = (rw + g) * QSTR + 8 * j + 2 * t;
                const int p1 = p0 + 8 * QSTR;
                *(unsigned*)&Ph[p0] = pk(h0, h1);
                *(unsigned*)&Pl[p0] = pk(l0, l1);
                *(unsigned*)&Ph[p1] = pk(h2, h3);
                *(unsigned*)&Pl[p1] = pk(l2, l3);
            }
            __syncwarp();

            // ---- O += P @ V ----
            #pragma unroll
            for (int ks = 0; ks < 4; ks++) {
                const int kk = 16 * ks;
                unsigned ph[4], plr[4];
                ldsm4(ph,  Ph + rw * QSTR + kk + aoffQ);
                ldsm4(plr, Pl + rw * QSTR + kk + aoffQ);
                #pragma unroll
                for (int jp = 0; jp < 4; jp++) {
                    unsigned bh[4], bl[4];
                    ldsm4(bh, Vh + (16 * jp) * QSTR + kk + boffQ);
                    ldsm4(bl, Vl + (16 * jp) * QSTR + kk + boffQ);
                    const int j0 = 2 * jp, j1 = j0 + 1;
                    mma16(o[j0], ph,  bh[0], bh[1]);
                    mma16(o[j0], plr, bh[0], bh[1]);
                    mma16(o[j0], ph,  bl[0], bl[1]);
                    mma16(o[j1], ph,  bh[2], bh[3]);
                    mma16(o[j1], plr, bh[2], bh[3]);
                    mma16(o[j1], ph,  bl[2], bl[3]);
                }
            }
        }
        __syncthreads();              // all done reading stage kt (free for kt+2)
    }

    // ---- normalize + split-write ctx ----
    const float inv0 = 1.f / l_i[0];
    const float inv1 = 1.f / l_i[1];
    const int row0 = qt * 128 + rw + g;
    const size_t d0 = ((size_t)b * SEQ + row0    ) * D_MODEL + h * D_HEAD;
    const size_t d1 = ((size_t)b * SEQ + row0 + 8) * D_MODEL + h * D_HEAD;
    #pragma unroll
    for (int j = 0; j < 8; j++) {
        const int cidx = 8 * j + 2 * t;
        __nv_bfloat16 h0, l0, h1, l1, h2, l2, h3, l3;
        split_bf(o[j][0] * inv0, h0, l0); split_bf(o[j][1] * inv0, h1, l1);
        split_bf(o[j][2] * inv1, h2, l2); split_bf(o[j][3] * inv1, h3, l3);
        *(unsigned*)&g_ch[d0 + cidx] = pk(h0, h1);
        *(unsigned*)&g_cl[d0 + cidx] = pk(l0, l1);
        *(unsigned*)&g_ch[d1 + cidx] = pk(h2, h3);
        *(unsigned*)&g_cl[d1 + cidx] = pk(l2, l3);
    }
}

// ---------------- launch ----------------------------------------------------
extern "C" void kernel_launch(void* const* d_in, const int* in_sizes, int n_in,
                              void* d_out, int out_size)
{
    (void)in_sizes; (void)n_in; (void)out_size;
    const float* x  = (const float*)d_in[0];
    const float* Qw = (const float*)d_in[1];
    const float* Kw = (const float*)d_in[2];
    const float* Vw = (const float*)d_in[3];
    const float* Ow = (const float*)d_in[4];
    const unsigned char* pm = (const unsigned char*)d_in[5];
    float* out = (float*)d_out;

    cudaFuncSetAttribute(attn_mma, cudaFuncAttributeMaxDynamicSharedMemorySize, ATTN_SMEM);
    cudaFuncSetAttribute(gemm_qkv, cudaFuncAttributeMaxDynamicSharedMemorySize, GEMM_SMEM);
    cudaFuncSetAttribute(gemm_out, cudaFuncAttributeMaxDynamicSharedMemorySize, GEMM_SMEM);

    split_all<<<12288, 256>>>(x, Qw, Kw, Vw, Ow);

    dim3 gq(D_MODEL / 128, MTOT / 128, 3);        // 8 x 64 x 3
    gemm_qkv<<<gq, 256, GEMM_SMEM>>>();

    dim3 ga(SEQ / 128, NUM_HEADS, BATCH);         // 16 x 16 x 4
    attn_mma<<<ga, 256, ATTN_SMEM>>>(pm);

    dim3 go(D_MODEL / 128, MTOT / 128);           // 8 x 64
    gemm_out<<<go, 256, GEMM_SMEM>>>(out);
}